// round 5
// baseline (speedup 1.0000x reference)
#include <cuda_runtime.h>
#include <math.h>

#define BB 8
#define LL 128
#define DD 512
#define EE 64
#define HH 8
#define BL (BB*LL)   // 1024

typedef unsigned long long ull;

__device__ __forceinline__ void fma2(ull &acc, ull a, ull b) {
    asm("fma.rn.f32x2 %0, %1, %2, %0;" : "+l"(acc) : "l"(a), "l"(b));
}
__device__ __forceinline__ void add2(ull &a, ull b) {
    asm("add.rn.f32x2 %0, %0, %1;" : "+l"(a) : "l"(b));
}
__device__ __forceinline__ ull pack2(float x, float y) {
    ull r; asm("mov.b64 %0, {%1,%2};" : "=l"(r) : "f"(x), "f"(y)); return r;
}
__device__ __forceinline__ void unpack2(ull v, float &x, float &y) {
    asm("mov.b64 {%0,%1}, %2;" : "=f"(x), "=f"(y) : "l"(v));
}
__device__ __forceinline__ float fsum2(ull v) {
    float x, y; unpack2(v, x, y); return x + y;
}

// Scratch
__device__ float dQ[BL*DD];
__device__ float dKV[BL*DD];
__device__ float dG[BL*HH*EE];           // [bq][h][e]
__device__ float dS1[BB*HH*LL*LL];       // [bh][q][k]
__device__ float dALPHA[BB*HH*LL*LL];    // [bh][q][k]
__device__ float dWsum[BB*HH*LL*EE];     // [bh][q][e]
__device__ float dATTN[BL*DD];
__device__ float dFFN[BL*DD];

// ---------------------------------------------------------------------------
// Double-buffered f32x2 GEMM: 64x64 tile, 128 threads, frag 8m x 4n.
// Smem stride 36 (16B-aligned rows; Bt reads stride-36 -> conflict-free LDS.64).
// ---------------------------------------------------------------------------
__global__ __launch_bounds__(128) void gemm_f2(
    const float* __restrict__ A,
    const float* __restrict__ B0, float* __restrict__ C0,
    const float* __restrict__ B1, float* __restrict__ C1,
    const float* __restrict__ bias, int K, int N)
{
    __shared__ float As[2][64*36];   // [m][kk]
    __shared__ float Bt[2][64*36];   // [n][kk] (k-pairs adjacent)

    const float* Bm = blockIdx.z ? B1 : B0;
    float*       Cm = blockIdx.z ? C1 : C0;

    const int t  = threadIdx.x;
    const int tx = t & 15, ty = t >> 4;           // ty 0..7
    const int m0 = blockIdx.y * 64, n0 = blockIdx.x * 64;

    float4 ar[4];
    float4 br0[2], br1[2];

    ull acc[8][4] = {};

    // prologue: load + stage tile 0
    {
        const int k0 = 0;
        #pragma unroll
        for (int r = 0; r < 4; r++) {
            int idx = t + r * 128; int m = idx >> 3; int k4 = (idx & 7) << 2;
            ar[r] = *(const float4*)(A + (size_t)(m0 + m) * K + k0 + k4);
        }
        #pragma unroll
        for (int r = 0; r < 2; r++) {
            int idx = t + r * 128; int kp = idx >> 4; int n4 = (idx & 15) << 2;
            br0[r] = *(const float4*)(Bm + (size_t)(k0 + 2*kp)     * N + n0 + n4);
            br1[r] = *(const float4*)(Bm + (size_t)(k0 + 2*kp + 1) * N + n0 + n4);
        }
        #pragma unroll
        for (int r = 0; r < 4; r++) {
            int idx = t + r * 128; int m = idx >> 3; int k4 = (idx & 7) << 2;
            *(float4*)(&As[0][m*36 + k4]) = ar[r];
        }
        #pragma unroll
        for (int r = 0; r < 2; r++) {
            int idx = t + r * 128; int kp = idx >> 4; int n4 = (idx & 15) << 2; int kk = kp*2;
            float4 v0 = br0[r], v1 = br1[r];
            *(float2*)(&Bt[0][(n4+0)*36 + kk]) = make_float2(v0.x, v1.x);
            *(float2*)(&Bt[0][(n4+1)*36 + kk]) = make_float2(v0.y, v1.y);
            *(float2*)(&Bt[0][(n4+2)*36 + kk]) = make_float2(v0.z, v1.z);
            *(float2*)(&Bt[0][(n4+3)*36 + kk]) = make_float2(v0.w, v1.w);
        }
    }

    const int NT = K / 32;
    int buf = 0;
    for (int kt = 0; kt < NT; kt++) {
        // load next tile into registers (overlaps with compute below)
        if (kt + 1 < NT) {
            const int k0 = (kt + 1) * 32;
            #pragma unroll
            for (int r = 0; r < 4; r++) {
                int idx = t + r * 128; int m = idx >> 3; int k4 = (idx & 7) << 2;
                ar[r] = *(const float4*)(A + (size_t)(m0 + m) * K + k0 + k4);
            }
            #pragma unroll
            for (int r = 0; r < 2; r++) {
                int idx = t + r * 128; int kp = idx >> 4; int n4 = (idx & 15) << 2;
                br0[r] = *(const float4*)(Bm + (size_t)(k0 + 2*kp)     * N + n0 + n4);
                br1[r] = *(const float4*)(Bm + (size_t)(k0 + 2*kp + 1) * N + n0 + n4);
            }
        }
        __syncthreads();   // buf staged & previous readers of buf^1 done

        #pragma unroll
        for (int kk = 0; kk < 32; kk += 2) {
            ull a[8], b[4];
            #pragma unroll
            for (int i = 0; i < 8; i++) a[i] = *(const ull*)(&As[buf][(ty*8 + i)*36 + kk]);
            #pragma unroll
            for (int j = 0; j < 4; j++) b[j] = *(const ull*)(&Bt[buf][(tx + 16*j)*36 + kk]);
            #pragma unroll
            for (int i = 0; i < 8; i++)
                #pragma unroll
                for (int j = 0; j < 4; j++)
                    fma2(acc[i][j], a[i], b[j]);
        }

        if (kt + 1 < NT) {
            int nb = buf ^ 1;
            #pragma unroll
            for (int r = 0; r < 4; r++) {
                int idx = t + r * 128; int m = idx >> 3; int k4 = (idx & 7) << 2;
                *(float4*)(&As[nb][m*36 + k4]) = ar[r];
            }
            #pragma unroll
            for (int r = 0; r < 2; r++) {
                int idx = t + r * 128; int kp = idx >> 4; int n4 = (idx & 15) << 2; int kk = kp*2;
                float4 v0 = br0[r], v1 = br1[r];
                *(float2*)(&Bt[nb][(n4+0)*36 + kk]) = make_float2(v0.x, v1.x);
                *(float2*)(&Bt[nb][(n4+1)*36 + kk]) = make_float2(v0.y, v1.y);
                *(float2*)(&Bt[nb][(n4+2)*36 + kk]) = make_float2(v0.z, v1.z);
                *(float2*)(&Bt[nb][(n4+3)*36 + kk]) = make_float2(v0.w, v1.w);
            }
            buf = nb;
        }
    }

    #pragma unroll
    for (int i = 0; i < 8; i++) {
        int m = m0 + ty * 8 + i;
        #pragma unroll
        for (int j = 0; j < 4; j++) {
            int n = n0 + tx + 16 * j;
            float v = fsum2(acc[i][j]);
            if (bias) v += bias[n];
            Cm[(size_t)m * N + n] = v;
        }
    }
}

// ---------------------------------------------------------------------------
// g[bq][h][e] = sum_c Q[bq, h*64+c] * We[e, h*64+c]
// ---------------------------------------------------------------------------
__global__ __launch_bounds__(256) void g_kernel(const float* __restrict__ We)
{
    __shared__ float Qs[64 * 65];
    __shared__ float Ws[64 * 65];

    const int t  = threadIdx.x;
    const int tx = t & 15, ty = t >> 4;
    const int r0 = blockIdx.x * 64;
    const int h  = blockIdx.y;

    #pragma unroll
    for (int r = 0; r < 4; r++) {
        int idx = t + r * 256;
        int m   = idx >> 4;
        int c4  = (idx & 15) << 2;
        float4 q = *(const float4*)(dQ + (size_t)(r0 + m) * DD + h * 64 + c4);
        Qs[m * 65 + c4 + 0] = q.x; Qs[m * 65 + c4 + 1] = q.y;
        Qs[m * 65 + c4 + 2] = q.z; Qs[m * 65 + c4 + 3] = q.w;
        float4 w = *(const float4*)(We + (size_t)m * DD + h * 64 + c4);
        Ws[m * 65 + c4 + 0] = w.x; Ws[m * 65 + c4 + 1] = w.y;
        Ws[m * 65 + c4 + 2] = w.z; Ws[m * 65 + c4 + 3] = w.w;
    }
    __syncthreads();

    float acc[4][4] = {};
    #pragma unroll
    for (int c = 0; c < 64; c++) {
        float a[4], b[4];
        #pragma unroll
        for (int i = 0; i < 4; i++) a[i] = Qs[(ty + 16 * i) * 65 + c];
        #pragma unroll
        for (int j = 0; j < 4; j++) b[j] = Ws[(tx + 16 * j) * 65 + c];
        #pragma unroll
        for (int i = 0; i < 4; i++)
            #pragma unroll
            for (int j = 0; j < 4; j++)
                acc[i][j] += a[i] * b[j];
    }

    #pragma unroll
    for (int i = 0; i < 4; i++) {
        int m = r0 + ty + 16 * i;
        #pragma unroll
        for (int j = 0; j < 4; j++)
            dG[((size_t)m * HH + h) * EE + tx + 16 * j] = acc[i][j];
    }
}

// ---------------------------------------------------------------------------
// S1: 64m x 128n per block, grid (64,2), 256 threads, frag 4m x 8n, f32x2
// ---------------------------------------------------------------------------
__global__ __launch_bounds__(256) void s1_f2()
{
    __shared__ float Qs[64 * 34];
    __shared__ float Ks[128 * 34];

    const int bh = blockIdx.x, mh = blockIdx.y;
    const int b  = bh >> 3, h = bh & 7;
    const int t  = threadIdx.x;
    const int tx = t & 15, ty = t >> 4;

    ull acc[4][8] = {};

    for (int c0 = 0; c0 < 64; c0 += 32) {
        #pragma unroll
        for (int r = 0; r < 2; r++) {
            int idx = t + r * 256;
            int m   = idx >> 3;
            int c4  = (idx & 7) << 2;
            float4 v = *(const float4*)(dQ + (size_t)(b * LL + mh * 64 + m) * DD + h * 64 + c0 + c4);
            *(float2*)(Qs + m * 34 + c4)     = make_float2(v.x, v.y);
            *(float2*)(Qs + m * 34 + c4 + 2) = make_float2(v.z, v.w);
        }
        #pragma unroll
        for (int r = 0; r < 4; r++) {
            int idx = t + r * 256;
            int n   = idx >> 3;
            int c4  = (idx & 7) << 2;
            float4 v = *(const float4*)(dKV + (size_t)(b * LL + n) * DD + h * 64 + c0 + c4);
            *(float2*)(Ks + n * 34 + c4)     = make_float2(v.x, v.y);
            *(float2*)(Ks + n * 34 + c4 + 2) = make_float2(v.z, v.w);
        }
        __syncthreads();

        #pragma unroll
        for (int cc = 0; cc < 32; cc += 2) {
            ull a[4], b2[8];
            #pragma unroll
            for (int i = 0; i < 4; i++) a[i]  = *(const ull*)(Qs + (ty * 4 + i) * 34 + cc);
            #pragma unroll
            for (int j = 0; j < 8; j++) b2[j] = *(const ull*)(Ks + (tx + 16 * j) * 34 + cc);
            #pragma unroll
            for (int i = 0; i < 4; i++)
                #pragma unroll
                for (int j = 0; j < 8; j++)
                    fma2(acc[i][j], a[i], b2[j]);
        }
        __syncthreads();
    }

    #pragma unroll
    for (int i = 0; i < 4; i++) {
        int m = mh * 64 + ty * 4 + i;
        #pragma unroll
        for (int j = 0; j < 8; j++)
            dS1[((size_t)bh * LL + m) * LL + tx + 16 * j] = fsum2(acc[i][j]);
    }
}

// ---------------------------------------------------------------------------
// Softmax: 256 threads per (b,q). Dots split 2-threads/key; Wsum split 4-way.
// f32x2 over head-pairs. smem 47.4KB.
// ---------------------------------------------------------------------------
__global__ __launch_bounds__(256) void softmax3(
    const float* __restrict__ eptr, const int* __restrict__ adj)
{
    __shared__ float es[128 * 68];   // [k][j]
    __shared__ float gT[64 * 8];     // [j][h]
    __shared__ float aT[128 * 8];    // [k][h]
    __shared__ float scr[1536];      // union: dot partials (1024) / wsum partials (1536)
    __shared__ float redM[4 * 8];
    __shared__ float redS[4 * 8];

    const int bq = blockIdx.x;
    const int b  = bq >> 7, q = bq & 127;
    const int t  = threadIdx.x;
    const int lane = t & 31, warp = t >> 5;

    // cooperative load of e[b,q,:,:] (128x64) and gT
    const float* erow = eptr + (size_t)bq * LL * EE;
    #pragma unroll
    for (int r = 0; r < 8; r++) {
        int idx = t + r * 256;
        int k   = idx >> 4;
        int j4  = (idx & 15) << 2;
        float4 v = *(const float4*)(erow + k * EE + j4);
        *(float4*)(es + k * 68 + j4) = v;
    }
    #pragma unroll
    for (int i0 = 0; i0 < 2; i0++) {
        int i = t + i0 * 256;
        int h = i >> 6, j = i & 63;
        gT[j * 8 + h] = dG[(size_t)bq * 512 + i];
    }
    __syncthreads();

    // phase A: partial dots. thread -> (k = t&127, j-half = t>>7)
    const int k  = t & 127;
    const int jh = t >> 7;
    ull acc2[4] = {0, 0, 0, 0};      // head pairs (01,23,45,67)
    #pragma unroll
    for (int j4 = 0; j4 < 8; j4++) {
        float4 ev4 = *(const float4*)(es + k * 68 + jh * 32 + j4 * 4);
        float evv[4] = {ev4.x, ev4.y, ev4.z, ev4.w};
        #pragma unroll
        for (int c = 0; c < 4; c++) {
            int j = jh * 32 + j4 * 4 + c;
            ull ed = pack2(evv[c], evv[c]);
            ulonglong2 g01 = *(const ulonglong2*)(gT + j * 8);
            ulonglong2 g23 = *(const ulonglong2*)(gT + j * 8 + 4);
            fma2(acc2[0], ed, g01.x); fma2(acc2[1], ed, g01.y);
            fma2(acc2[2], ed, g23.x); fma2(acc2[3], ed, g23.y);
        }
    }
    if (jh == 1) {
        *(ulonglong2*)(scr + k * 8)     = make_ulonglong2(acc2[0], acc2[1]);
        *(ulonglong2*)(scr + k * 8 + 4) = make_ulonglong2(acc2[2], acc2[3]);
    }
    __syncthreads();

    // phase B: softmax (threads t<128, key k=t)
    float sv[8];
    if (t < 128) {
        ulonglong2 p01 = *(const ulonglong2*)(scr + k * 8);
        ulonglong2 p23 = *(const ulonglong2*)(scr + k * 8 + 4);
        add2(acc2[0], p01.x); add2(acc2[1], p01.y);
        add2(acc2[2], p23.x); add2(acc2[3], p23.y);
        unpack2(acc2[0], sv[0], sv[1]);
        unpack2(acc2[1], sv[2], sv[3]);
        unpack2(acc2[2], sv[4], sv[5]);
        unpack2(acc2[3], sv[6], sv[7]);
        const int adjv = adj[(size_t)bq * LL + k];
        #pragma unroll
        for (int h = 0; h < HH; h++) {
            float s = (dS1[(((size_t)(b * HH + h)) * LL + q) * LL + k] + sv[h]) * 0.125f;
            s = (s > 0.f) ? s : 0.2f * s;
            if (adjv == 0) s = -1e9f;
            sv[h] = s;
        }
        #pragma unroll
        for (int h = 0; h < HH; h++) {
            float m = sv[h];
            #pragma unroll
            for (int o = 16; o > 0; o >>= 1) m = fmaxf(m, __shfl_xor_sync(0xffffffffu, m, o));
            if (lane == 0) redM[warp * 8 + h] = m;
        }
    }
    __syncthreads();

    float p[8];
    if (t < 128) {
        #pragma unroll
        for (int h = 0; h < HH; h++) {
            float mx = fmaxf(fmaxf(redM[h], redM[8 + h]), fmaxf(redM[16 + h], redM[24 + h]));
            p[h] = __expf(sv[h] - mx);
        }
        #pragma unroll
        for (int h = 0; h < HH; h++) {
            float s = p[h];
            #pragma unroll
            for (int o = 16; o > 0; o >>= 1) s += __shfl_xor_sync(0xffffffffu, s, o);
            if (lane == 0) redS[warp * 8 + h] = s;
        }
    }
    __syncthreads();

    if (t < 128) {
        float al[8];
        #pragma unroll
        for (int h = 0; h < HH; h++) {
            float tot = redS[h] + redS[8 + h] + redS[16 + h] + redS[24 + h];
            al[h] = p[h] / tot;
            dALPHA[(((size_t)(b * HH + h)) * LL + q) * LL + k] = al[h];
        }
        *(float4*)(aT + k * 8)     = make_float4(al[0], al[1], al[2], al[3]);
        *(float4*)(aT + k * 8 + 4) = make_float4(al[4], al[5], al[6], al[7]);
    }
    __syncthreads();

    // phase C: Wsum. thread -> (ei = t&63, k-quarter = t>>6)
    const int ei = t & 63, qt = t >> 6;
    ull w2[4] = {0, 0, 0, 0};
    #pragma unroll 8
    for (int kk = 0; kk < 32; kk++) {
        int kq = qt * 32 + kk;
        float ev = es[kq * 68 + ei];
        ull ed = pack2(ev, ev);
        ulonglong2 a01 = *(const ulonglong2*)(aT + kq * 8);
        ulonglong2 a23 = *(const ulonglong2*)(aT + kq * 8 + 4);
        fma2(w2[0], ed, a01.x); fma2(w2[1], ed, a01.y);
        fma2(w2[2], ed, a23.x); fma2(w2[3], ed, a23.y);
    }
    if (qt > 0) {
        *(ulonglong2*)(scr + ((qt - 1) * 64 + ei) * 8)     = make_ulonglong2(w2[0], w2[1]);
        *(ulonglong2*)(scr + ((qt - 1) * 64 + ei) * 8 + 4) = make_ulonglong2(w2[2], w2[3]);
    }
    __syncthreads();
    if (qt == 0) {
        #pragma unroll
        for (int p2 = 0; p2 < 3; p2++) {
            ulonglong2 s01 = *(const ulonglong2*)(scr + (p2 * 64 + ei) * 8);
            ulonglong2 s23 = *(const ulonglong2*)(scr + (p2 * 64 + ei) * 8 + 4);
            add2(w2[0], s01.x); add2(w2[1], s01.y);
            add2(w2[2], s23.x); add2(w2[3], s23.y);
        }
        float w[8];
        unpack2(w2[0], w[0], w[1]); unpack2(w2[1], w[2], w[3]);
        unpack2(w2[2], w[4], w[5]); unpack2(w2[3], w[6], w[7]);
        #pragma unroll
        for (int h = 0; h < HH; h++)
            dWsum[(((size_t)(b * HH + h)) * LL + q) * EE + ei] = w[h];
    }
}

// ---------------------------------------------------------------------------
// ATTN = alpha@KV + Wsum@We_h : 64x64 tile, K=192, f32x2, grid (64,2)
// ---------------------------------------------------------------------------
__global__ __launch_bounds__(128) void attn_f2(const float* __restrict__ We)
{
    __shared__ float As[64 * 34];
    __shared__ float Bt[64 * 34];

    const int bh = blockIdx.x, mh = blockIdx.y;
    const int b  = bh >> 3, h = bh & 7;
    const int t  = threadIdx.x;
    const int tx = t & 15, ty = t >> 4;

    ull acc[8][4] = {};

    for (int k0 = 0; k0 < 192; k0 += 32) {
        #pragma unroll
        for (int r = 0; r < 4; r++) {
            int idx = t + r * 128;
            int m   = idx >> 3;
            int k4  = (idx & 7) << 2;
            size_t row = (size_t)bh * LL + mh * 64 + m;
            float4 v;
            if (k0 < 128) v = *(const float4*)(dALPHA + row * LL + k0 + k4);
            else          v = *(const float4*)(dWsum  + row * EE + (k0 - 128) + k4);
            *(float2*)(As + m * 34 + k4)     = make_float2(v.x, v.y);
            *(float2*)(As + m * 34 + k4 + 2) = make_float2(v.z, v.w);
        }
        #pragma unroll
        for (int r = 0; r < 2; r++) {
            int idx = t + r * 128;
            int kp  = idx >> 4;
            int n4  = (idx & 15) << 2;
            int kk  = kp * 2;
            int kg  = k0 + kk;
            float4 v0, v1;
            if (kg < 128) {
                v0 = *(const float4*)(dKV + (size_t)(b * LL + kg)     * DD + h * 64 + n4);
                v1 = *(const float4*)(dKV + (size_t)(b * LL + kg + 1) * DD + h * 64 + n4);
            } else {
                v0 = *(const float4*)(We + (size_t)(kg - 128) * DD + h * 64 + n4);
                v1 = *(const float4*)(We + (size_t)(kg - 127) * DD + h * 64 + n4);
            }
            *(float2*)(Bt + (n4 + 0) * 34 + kk) = make_float2(v0.x, v1.x);
            *(float2*)(Bt + (n4 + 1) * 34 + kk) = make_float2(v0.y, v1.y);
            *(float2*)(Bt + (n4 + 2) * 34 + kk) = make_float2(v0.z, v1.z);
            *(float2*)(Bt + (n4 + 3) * 34 + kk) = make_float2(v0.w, v1.w);
        }
        __syncthreads();

        #pragma unroll
        for (int kk = 0; kk < 32; kk += 2) {
            ull a[8], b2[4];
            #pragma unroll
            for (int i = 0; i < 8; i++) a[i]  = *(const ull*)(As + (ty * 8 + i) * 34 + kk);
            #pragma unroll
            for (int j = 0; j < 4; j++) b2[j] = *(const ull*)(Bt + (tx + 16 * j) * 34 + kk);
            #pragma unroll
            for (int i = 0; i < 8; i++)
                #pragma unroll
                for (int j = 0; j < 4; j++)
                    fma2(acc[i][j], a[i], b2[j]);
        }
        __syncthreads();
    }

    #pragma unroll
    for (int i = 0; i < 8; i++) {
        int m = mh * 64 + ty * 8 + i;
        #pragma unroll
        for (int j = 0; j < 4; j++) {
            int n = tx + 16 * j;
            dATTN[((size_t)(b * LL) + m) * DD + h * 64 + n] = fsum2(acc[i][j]);
        }
    }
}

// ---------------------------------------------------------------------------
// LayerNorm + ReLU per row of 512
// ---------------------------------------------------------------------------
__global__ __launch_bounds__(256) void ln_kernel(
    const float* __restrict__ gamma, const float* __restrict__ beta,
    float* __restrict__ out)
{
    const int r = blockIdx.x;
    const int t = threadIdx.x;
    const int lane = t & 31, warp = t >> 5;

    float v0 = dFFN[(size_t)r * DD + t];
    float v1 = dFFN[(size_t)r * DD + 256 + t];
    float s  = v0 + v1;
    float sq = v0 * v0 + v1 * v1;

    __shared__ float rs[8], rq[8];
    __shared__ float mu_s, rstd_s;
    #pragma unroll
    for (int o = 16; o > 0; o >>= 1) {
        s  += __shfl_xor_sync(0xffffffffu, s, o);
        sq += __shfl_xor_sync(0xffffffffu, sq, o);
    }
    if (lane == 0) { rs[warp] = s; rq[warp] = sq; }
    __syncthreads();
    if (t == 0) {
        float S = 0.f, Q2 = 0.f;
        #pragma unroll
        for (int w = 0; w < 8; w++) { S += rs[w]; Q2 += rq[w]; }
        float mu  = S / 512.f;
        float var = Q2 / 512.f - mu * mu;
        mu_s = mu;
        rstd_s = rsqrtf(var + 1e-5f);
    }
    __syncthreads();
    float mu = mu_s, rstd = rstd_s;

    float y0 = (v0 - mu) * rstd * gamma[t]       + beta[t];
    float y1 = (v1 - mu) * rstd * gamma[256 + t] + beta[256 + t];
    out[(size_t)r * DD + t]       = fmaxf(y0, 0.f);
    out[(size_t)r * DD + 256 + t] = fmaxf(y1, 0.f);
}

// ---------------------------------------------------------------------------
extern "C" void kernel_launch(void* const* d_in, const int* in_sizes, int n_in,
                              void* d_out, int out_size)
{
    const float* x     = (const float*)d_in[0];
    const int*   adj   = (const int*)  d_in[1];
    const float* e     = (const float*)d_in[2];
    const float* Wq    = (const float*)d_in[3];
    const float* Wkv   = (const float*)d_in[4];
    const float* We    = (const float*)d_in[5];
    const float* Wf    = (const float*)d_in[6];
    const float* bf    = (const float*)d_in[7];
    const float* gamma = (const float*)d_in[8];
    const float* beta  = (const float*)d_in[9];
    float* out = (float*)d_out;

    float *pQ, *pKV, *pATTN, *pFFN;
    cudaGetSymbolAddress((void**)&pQ,    dQ);
    cudaGetSymbolAddress((void**)&pKV,   dKV);
    cudaGetSymbolAddress((void**)&pATTN, dATTN);
    cudaGetSymbolAddress((void**)&pFFN,  dFFN);

    // 1. Q = x@Wq, KV = x@Wkv
    gemm_f2<<<dim3(DD/64, BL/64, 2), 128>>>(x, Wq, pQ, Wkv, pKV, nullptr, DD, DD);
    // 2. g = We_h^T q_h
    g_kernel<<<dim3(BL/64, HH), 256>>>(We);
    // 3. S1 = Q_h @ KV_h^T
    s1_f2<<<dim3(BB*HH, 2), 256>>>();
    // 4. softmax + alpha-weighted e reduction (256 threads, all heads one pass)
    softmax3<<<BL, 256>>>(e, adj);
    // 5. attention output
    attn_f2<<<dim3(BB*HH, 2), 128>>>(We);
    // 6. FFN GEMM with bias
    gemm_f2<<<dim3(DD/64, BL/64, 1), 128>>>(pATTN, Wf, pFFN, nullptr, nullptr, bf, DD, DD);
    // 7. LayerNorm + ReLU
    ln_kernel<<<BL, 256>>>(gamma, beta, out);
}

// round 7
// speedup vs baseline: 1.0057x; 1.0057x over previous
#include <cuda_runtime.h>
#include <math.h>

#define BB 8
#define LL 128
#define DD 512
#define EE 64
#define HH 8
#define BL (BB*LL)   // 1024

typedef unsigned long long ull;

__device__ __forceinline__ void fma2(ull &acc, ull a, ull b) {
    asm("fma.rn.f32x2 %0, %1, %2, %0;" : "+l"(acc) : "l"(a), "l"(b));
}
__device__ __forceinline__ void add2(ull &a, ull b) {
    asm("add.rn.f32x2 %0, %0, %1;" : "+l"(a) : "l"(b));
}
__device__ __forceinline__ ull pack2(float x, float y) {
    ull r; asm("mov.b64 %0, {%1,%2};" : "=l"(r) : "f"(x), "f"(y)); return r;
}
__device__ __forceinline__ void unpack2(ull v, float &x, float &y) {
    asm("mov.b64 {%0,%1}, %2;" : "=f"(x), "=f"(y) : "l"(v));
}
__device__ __forceinline__ float fsum2(ull v) {
    float x, y; unpack2(v, x, y); return x + y;
}

// Scratch
__device__ float dQ[BL*DD];
__device__ float dKV[BL*DD];
__device__ float dG[BL*HH*EE];           // [bq][h][e]
__device__ float dS1[BB*HH*LL*LL];       // [bh][q][k]
__device__ float dALPHA[BB*HH*LL*LL];    // [bh][q][k]
__device__ float dWsum[BB*HH*LL*EE];     // [bh][q][e]
__device__ float dATTN[BL*DD];
__device__ float dFFN[BL*DD];

// ---------------------------------------------------------------------------
// f32x2 GEMM (R4 single-buffer — proven best): 64x64 tile, 128 threads,
// frag 8m x 4n, K paired, smem stride 34.
// ---------------------------------------------------------------------------
__global__ __launch_bounds__(128) void gemm_f2(
    const float* __restrict__ A,
    const float* __restrict__ B0, float* __restrict__ C0,
    const float* __restrict__ B1, float* __restrict__ C1,
    const float* __restrict__ bias, int K, int N)
{
    __shared__ float As[64*34];    // [m][kk]
    __shared__ float Bt[64*34];    // [n][kk]

    const float* Bm = blockIdx.z ? B1 : B0;
    float*       Cm = blockIdx.z ? C1 : C0;

    const int t  = threadIdx.x;
    const int tx = t & 15, ty = t >> 4;           // ty 0..7
    const int m0 = blockIdx.y * 64, n0 = blockIdx.x * 64;

    ull acc[8][4] = {};

    for (int k0 = 0; k0 < K; k0 += 32) {
        #pragma unroll
        for (int r = 0; r < 4; r++) {
            int idx = t + r * 128;
            int m   = idx >> 3;
            int k4  = (idx & 7) << 2;
            float4 v = *(const float4*)(A + (size_t)(m0 + m) * K + k0 + k4);
            *(float2*)(As + m * 34 + k4)     = make_float2(v.x, v.y);
            *(float2*)(As + m * 34 + k4 + 2) = make_float2(v.z, v.w);
        }
        #pragma unroll
        for (int r = 0; r < 2; r++) {
            int idx = t + r * 128;
            int kp  = idx >> 4;
            int n4  = (idx & 15) << 2;
            int kk  = kp * 2;
            float4 v0 = *(const float4*)(Bm + (size_t)(k0 + kk)     * N + n0 + n4);
            float4 v1 = *(const float4*)(Bm + (size_t)(k0 + kk + 1) * N + n0 + n4);
            *(float2*)(Bt + (n4 + 0) * 34 + kk) = make_float2(v0.x, v1.x);
            *(float2*)(Bt + (n4 + 1) * 34 + kk) = make_float2(v0.y, v1.y);
            *(float2*)(Bt + (n4 + 2) * 34 + kk) = make_float2(v0.z, v1.z);
            *(float2*)(Bt + (n4 + 3) * 34 + kk) = make_float2(v0.w, v1.w);
        }
        __syncthreads();

        #pragma unroll
        for (int kk = 0; kk < 32; kk += 2) {
            ull a[8], b[4];
            #pragma unroll
            for (int i = 0; i < 8; i++) a[i] = *(const ull*)(As + (ty * 8 + i) * 34 + kk);
            #pragma unroll
            for (int j = 0; j < 4; j++) b[j] = *(const ull*)(Bt + (tx + 16 * j) * 34 + kk);
            #pragma unroll
            for (int i = 0; i < 8; i++)
                #pragma unroll
                for (int j = 0; j < 4; j++)
                    fma2(acc[i][j], a[i], b[j]);
        }
        __syncthreads();
    }

    #pragma unroll
    for (int i = 0; i < 8; i++) {
        int m = m0 + ty * 8 + i;
        #pragma unroll
        for (int j = 0; j < 4; j++) {
            int n = n0 + tx + 16 * j;
            float v = fsum2(acc[i][j]);
            if (bias) v += bias[n];
            Cm[(size_t)m * N + n] = v;
        }
    }
}

// ---------------------------------------------------------------------------
// g[bq][h][e] = sum_c Q[bq, h*64+c] * We[e, h*64+c]
// ---------------------------------------------------------------------------
__global__ __launch_bounds__(256) void g_kernel(const float* __restrict__ We)
{
    __shared__ float Qs[64 * 65];
    __shared__ float Ws[64 * 65];

    const int t  = threadIdx.x;
    const int tx = t & 15, ty = t >> 4;
    const int r0 = blockIdx.x * 64;
    const int h  = blockIdx.y;

    #pragma unroll
    for (int r = 0; r < 4; r++) {
        int idx = t + r * 256;
        int m   = idx >> 4;
        int c4  = (idx & 15) << 2;
        float4 q = *(const float4*)(dQ + (size_t)(r0 + m) * DD + h * 64 + c4);
        Qs[m * 65 + c4 + 0] = q.x; Qs[m * 65 + c4 + 1] = q.y;
        Qs[m * 65 + c4 + 2] = q.z; Qs[m * 65 + c4 + 3] = q.w;
        float4 w = *(const float4*)(We + (size_t)m * DD + h * 64 + c4);
        Ws[m * 65 + c4 + 0] = w.x; Ws[m * 65 + c4 + 1] = w.y;
        Ws[m * 65 + c4 + 2] = w.z; Ws[m * 65 + c4 + 3] = w.w;
    }
    __syncthreads();

    float acc[4][4] = {};
    #pragma unroll
    for (int c = 0; c < 64; c++) {
        float a[4], b[4];
        #pragma unroll
        for (int i = 0; i < 4; i++) a[i] = Qs[(ty + 16 * i) * 65 + c];
        #pragma unroll
        for (int j = 0; j < 4; j++) b[j] = Ws[(tx + 16 * j) * 65 + c];
        #pragma unroll
        for (int i = 0; i < 4; i++)
            #pragma unroll
            for (int j = 0; j < 4; j++)
                acc[i][j] += a[i] * b[j];
    }

    #pragma unroll
    for (int i = 0; i < 4; i++) {
        int m = r0 + ty + 16 * i;
        #pragma unroll
        for (int j = 0; j < 4; j++)
            dG[((size_t)m * HH + h) * EE + tx + 16 * j] = acc[i][j];
    }
}

// ---------------------------------------------------------------------------
// S1: 64m x 128n per block, grid (64,2), 256 threads, frag 4m x 8n, f32x2
// ---------------------------------------------------------------------------
__global__ __launch_bounds__(256) void s1_f2()
{
    __shared__ float Qs[64 * 34];
    __shared__ float Ks[128 * 34];

    const int bh = blockIdx.x, mh = blockIdx.y;
    const int b  = bh >> 3, h = bh & 7;
    const int t  = threadIdx.x;
    const int tx = t & 15, ty = t >> 4;

    ull acc[4][8] = {};

    for (int c0 = 0; c0 < 64; c0 += 32) {
        #pragma unroll
        for (int r = 0; r < 2; r++) {
            int idx = t + r * 256;
            int m   = idx >> 3;
            int c4  = (idx & 7) << 2;
            float4 v = *(const float4*)(dQ + (size_t)(b * LL + mh * 64 + m) * DD + h * 64 + c0 + c4);
            *(float2*)(Qs + m * 34 + c4)     = make_float2(v.x, v.y);
            *(float2*)(Qs + m * 34 + c4 + 2) = make_float2(v.z, v.w);
        }
        #pragma unroll
        for (int r = 0; r < 4; r++) {
            int idx = t + r * 256;
            int n   = idx >> 3;
            int c4  = (idx & 7) << 2;
            float4 v = *(const float4*)(dKV + (size_t)(b * LL + n) * DD + h * 64 + c0 + c4);
            *(float2*)(Ks + n * 34 + c4)     = make_float2(v.x, v.y);
            *(float2*)(Ks + n * 34 + c4 + 2) = make_float2(v.z, v.w);
        }
        __syncthreads();

        #pragma unroll
        for (int cc = 0; cc < 32; cc += 2) {
            ull a[4], b2[8];
            #pragma unroll
            for (int i = 0; i < 4; i++) a[i]  = *(const ull*)(Qs + (ty * 4 + i) * 34 + cc);
            #pragma unroll
            for (int j = 0; j < 8; j++) b2[j] = *(const ull*)(Ks + (tx + 16 * j) * 34 + cc);
            #pragma unroll
            for (int i = 0; i < 4; i++)
                #pragma unroll
                for (int j = 0; j < 8; j++)
                    fma2(acc[i][j], a[i], b2[j]);
        }
        __syncthreads();
    }

    #pragma unroll
    for (int i = 0; i < 4; i++) {
        int m = mh * 64 + ty * 4 + i;
        #pragma unroll
        for (int j = 0; j < 8; j++)
            dS1[((size_t)bh * LL + m) * LL + tx + 16 * j] = fsum2(acc[i][j]);
    }
}

// ---------------------------------------------------------------------------
// Softmax v4: 256 threads per (b,q), all 8 heads, smem trimmed to ~41.2KB via
// buffer aliasing so 5 blocks/SM fit (227KB smem/SM).
//   aT buffer: dot-partials (phase A) -> alpha (phase B) -> Wsum partials q1/q2
//   gT buffer: g (phase A) -> Wsum partials q3
// Aliasing safety: every reuse is separated by __syncthreads() after all reads.
// ---------------------------------------------------------------------------
__global__ __launch_bounds__(256, 5) void softmax4(
    const float* __restrict__ eptr, const int* __restrict__ adj)
{
    __shared__ float es[128 * 68];   // 34.8 KB  [k][j]
    __shared__ float gT[512];        // 2 KB     [j][h]; later q3 wsum partials
    __shared__ float aT[1024];       // 4 KB     dot partials / [k][h] alpha / q1,q2 partials
    __shared__ float redM[32];
    __shared__ float redS[32];

    const int bq = blockIdx.x;
    const int b  = bq >> 7, q = bq & 127;
    const int t  = threadIdx.x;
    const int lane = t & 31, warp = t >> 5;

    // load e[b,q,:,:] (128x64) and gT
    const float* erow = eptr + (size_t)bq * LL * EE;
    #pragma unroll
    for (int r = 0; r < 8; r++) {
        int idx = t + r * 256;
        int k   = idx >> 4;
        int j4  = (idx & 15) << 2;
        float4 v = *(const float4*)(erow + k * EE + j4);
        *(float4*)(es + k * 68 + j4) = v;
    }
    #pragma unroll
    for (int i0 = 0; i0 < 2; i0++) {
        int i = t + i0 * 256;
        int h = i >> 6, j = i & 63;
        gT[j * 8 + h] = dG[(size_t)bq * 512 + i];
    }
    __syncthreads();

    // ---- phase A: partial dots. thread -> (k = t&127, j-half = t>>7) ----
    const int k  = t & 127;
    const int jh = t >> 7;
    ull acc2[4] = {0, 0, 0, 0};      // head pairs (01,23,45,67)
    #pragma unroll
    for (int j4 = 0; j4 < 8; j4++) {
        float4 ev4 = *(const float4*)(es + k * 68 + jh * 32 + j4 * 4);
        float evv[4] = {ev4.x, ev4.y, ev4.z, ev4.w};
        #pragma unroll
        for (int c = 0; c < 4; c++) {
            int j = jh * 32 + j4 * 4 + c;
            ull ed = pack2(evv[c], evv[c]);
            ulonglong2 g01 = *(const ulonglong2*)(gT + j * 8);
            ulonglong2 g23 = *(const ulonglong2*)(gT + j * 8 + 4);
            fma2(acc2[0], ed, g01.x); fma2(acc2[1], ed, g01.y);
            fma2(acc2[2], ed, g23.x); fma2(acc2[3], ed, g23.y);
        }
    }
    if (jh == 1) {   // write my partial into aT (dot-partial role)
        *(ulonglong2*)(aT + k * 8)     = make_ulonglong2(acc2[0], acc2[1]);
        *(ulonglong2*)(aT + k * 8 + 4) = make_ulonglong2(acc2[2], acc2[3]);
    }
    __syncthreads();

    // ---- phase B: softmax over keys (threads t<128, key k=t) ----
    float sv[8];
    if (t < 128) {
        ulonglong2 p01 = *(const ulonglong2*)(aT + k * 8);
        ulonglong2 p23 = *(const ulonglong2*)(aT + k * 8 + 4);
        add2(acc2[0], p01.x); add2(acc2[1], p01.y);
        add2(acc2[2], p23.x); add2(acc2[3], p23.y);
        unpack2(acc2[0], sv[0], sv[1]);
        unpack2(acc2[1], sv[2], sv[3]);
        unpack2(acc2[2], sv[4], sv[5]);
        unpack2(acc2[3], sv[6], sv[7]);
        const int adjv = adj[(size_t)bq * LL + k];
        #pragma unroll
        for (int h = 0; h < HH; h++) {
            float s = (dS1[(((size_t)(b * HH + h)) * LL + q) * LL + k] + sv[h]) * 0.125f;
            s = (s > 0.f) ? s : 0.2f * s;
            if (adjv == 0) s = -1e9f;
            sv[h] = s;
        }
        #pragma unroll
        for (int h = 0; h < HH; h++) {
            float m = sv[h];
            #pragma unroll
            for (int o = 16; o > 0; o >>= 1) m = fmaxf(m, __shfl_xor_sync(0xffffffffu, m, o));
            if (lane == 0) redM[warp * 8 + h] = m;
        }
    }
    __syncthreads();   // also guarantees all aT dot-partial reads are done

    float p[8];
    if (t < 128) {
        #pragma unroll
        for (int h = 0; h < HH; h++) {
            float mx = fmaxf(fmaxf(redM[h], redM[8 + h]), fmaxf(redM[16 + h], redM[24 + h]));
            p[h] = __expf(sv[h] - mx);
        }
        #pragma unroll
        for (int h = 0; h < HH; h++) {
            float s = p[h];
            #pragma unroll
            for (int o = 16; o > 0; o >>= 1) s += __shfl_xor_sync(0xffffffffu, s, o);
            if (lane == 0) redS[warp * 8 + h] = s;
        }
    }
    __syncthreads();

    if (t < 128) {
        float al[8];
        #pragma unroll
        for (int h = 0; h < HH; h++) {
            float tot = redS[h] + redS[8 + h] + redS[16 + h] + redS[24 + h];
            al[h] = p[h] / tot;
            dALPHA[(((size_t)(b * HH + h)) * LL + q) * LL + k] = al[h];
        }
        // aT now takes its alpha role
        *(float4*)(aT + k * 8)     = make_float4(al[0], al[1], al[2], al[3]);
        *(float4*)(aT + k * 8 + 4) = make_float4(al[4], al[5], al[6], al[7]);
    }
    __syncthreads();

    // ---- phase C: Wsum. thread -> (ei = t&63, k-quarter qt = t>>6) ----
    const int ei = t & 63, qt = t >> 6;
    ull w2[4] = {0, 0, 0, 0};
    #pragma unroll 8
    for (int kk = 0; kk < 32; kk++) {
        int kq = qt * 32 + kk;
        float ev = es[kq * 68 + ei];
        ull ed = pack2(ev, ev);
        ulonglong2 a01 = *(const ulonglong2*)(aT + kq * 8);
        ulonglong2 a23 = *(const ulonglong2*)(aT + kq * 8 + 4);
        fma2(w2[0], ed, a01.x); fma2(w2[1], ed, a01.y);
        fma2(w2[2], ed, a23.x); fma2(w2[3], ed, a23.y);
    }
    __syncthreads();   // all alpha (aT) reads done -> safe to overwrite

    // partials: q1 -> aT[0:512], q2 -> aT[512:1024], q3 -> gT[0:512]
    if (qt == 1) {
        *(ulonglong2*)(aT + ei * 8)       = make_ulonglong2(w2[0], w2[1]);
        *(ulonglong2*)(aT + ei * 8 + 4)   = make_ulonglong2(w2[2], w2[3]);
    } else if (qt == 2) {
        *(ulonglong2*)(aT + 512 + ei * 8)     = make_ulonglong2(w2[0], w2[1]);
        *(ulonglong2*)(aT + 512 + ei * 8 + 4) = make_ulonglong2(w2[2], w2[3]);
    } else if (qt == 3) {
        *(ulonglong2*)(gT + ei * 8)       = make_ulonglong2(w2[0], w2[1]);
        *(ulonglong2*)(gT + ei * 8 + 4)   = make_ulonglong2(w2[2], w2[3]);
    }
    __syncthreads();

    if (qt == 0) {
        ulonglong2 s1a = *(const ulonglong2*)(aT + ei * 8);
        ulonglong2 s1b = *(const ulonglong2*)(aT + ei * 8 + 4);
        ulonglong2 s2a = *(const ulonglong2*)(aT + 512 + ei * 8);
        ulonglong2 s2b = *(const ulonglong2*)(aT + 512 + ei * 8 + 4);
        ulonglong2 s3a = *(const ulonglong2*)(gT + ei * 8);
        ulonglong2 s3b = *(const ulonglong2*)(gT + ei * 8 + 4);
        add2(w2[0], s1a.x); add2(w2[1], s1a.y); add2(w2[2], s1b.x); add2(w2[3], s1b.y);
        add2(w2[0], s2a.x); add2(w2[1], s2a.y); add2(w2[2], s2b.x); add2(w2[3], s2b.y);
        add2(w2[0], s3a.x); add2(w2[1], s3a.y); add2(w2[2], s3b.x); add2(w2[3], s3b.y);
        float w[8];
        unpack2(w2[0], w[0], w[1]); unpack2(w2[1], w[2], w[3]);
        unpack2(w2[2], w[4], w[5]); unpack2(w2[3], w[6], w[7]);
        #pragma unroll
        for (int h = 0; h < HH; h++)
            dWsum[(((size_t)(b * HH + h)) * LL + q) * EE + ei] = w[h];
    }
}

// ---------------------------------------------------------------------------
// ATTN = alpha@KV + Wsum@We_h : 64x64 tile, K=192, f32x2, grid (64,2)
// ---------------------------------------------------------------------------
__global__ __launch_bounds__(128) void attn_f2(const float* __restrict__ We)
{
    __shared__ float As[64 * 34];
    __shared__ float Bt[64 * 34];

    const int bh = blockIdx.x, mh = blockIdx.y;
    const int b  = bh >> 3, h = bh & 7;
    const int t  = threadIdx.x;
    const int tx = t & 15, ty = t >> 4;

    ull acc[8][4] = {};

    for (int k0 = 0; k0 < 192; k0 += 32) {
        #pragma unroll
        for (int r = 0; r < 4; r++) {
            int idx = t + r * 128;
            int m   = idx >> 3;
            int k4  = (idx & 7) << 2;
            size_t row = (size_t)bh * LL + mh * 64 + m;
            float4 v;
            if (k0 < 128) v = *(const float4*)(dALPHA + row * LL + k0 + k4);
            else          v = *(const float4*)(dWsum  + row * EE + (k0 - 128) + k4);
            *(float2*)(As + m * 34 + k4)     = make_float2(v.x, v.y);
            *(float2*)(As + m * 34 + k4 + 2) = make_float2(v.z, v.w);
        }
        #pragma unroll
        for (int r = 0; r < 2; r++) {
            int idx = t + r * 128;
            int kp  = idx >> 4;
            int n4  = (idx & 15) << 2;
            int kk  = kp * 2;
            int kg  = k0 + kk;
            float4 v0, v1;
            if (kg < 128) {
                v0 = *(const float4*)(dKV + (size_t)(b * LL + kg)     * DD + h * 64 + n4);
                v1 = *(const float4*)(dKV + (size_t)(b * LL + kg + 1) * DD + h * 64 + n4);
            } else {
                v0 = *(const float4*)(We + (size_t)(kg - 128) * DD + h * 64 + n4);
                v1 = *(const float4*)(We + (size_t)(kg - 127) * DD + h * 64 + n4);
            }
            *(float2*)(Bt + (n4 + 0) * 34 + kk) = make_float2(v0.x, v1.x);
            *(float2*)(Bt + (n4 + 1) * 34 + kk) = make_float2(v0.y, v1.y);
            *(float2*)(Bt + (n4 + 2) * 34 + kk) = make_float2(v0.z, v1.z);
            *(float2*)(Bt + (n4 + 3) * 34 + kk) = make_float2(v0.w, v1.w);
        }
        __syncthreads();

        #pragma unroll
        for (int kk = 0; kk < 32; kk += 2) {
            ull a[8], b2[4];
            #pragma unroll
            for (int i = 0; i < 8; i++) a[i]  = *(const ull*)(As + (ty * 8 + i) * 34 + kk);
            #pragma unroll
            for (int j = 0; j < 4; j++) b2[j] = *(const ull*)(Bt + (tx + 16 * j) * 34 + kk);
            #pragma unroll
            for (int i = 0; i < 8; i++)
                #pragma unroll
                for (int j = 0; j < 4; j++)
                    fma2(acc[i][j], a[i], b2[j]);
        }
        __syncthreads();
    }

    #pragma unroll
    for (int i = 0; i < 8; i++) {
        int m = mh * 64 + ty * 8 + i;
        #pragma unroll
        for (int j = 0; j < 4; j++) {
            int n = tx + 16 * j;
            dATTN[((size_t)(b * LL) + m) * DD + h * 64 + n] = fsum2(acc[i][j]);
        }
    }
}

// ---------------------------------------------------------------------------
// LayerNorm + ReLU per row of 512
// ---------------------------------------------------------------------------
__global__ __launch_bounds__(256) void ln_kernel(
    const float* __restrict__ gamma, const float* __restrict__ beta,
    float* __restrict__ out)
{
    const int r = blockIdx.x;
    const int t = threadIdx.x;
    const int lane = t & 31, warp = t >> 5;

    float v0 = dFFN[(size_t)r * DD + t];
    float v1 = dFFN[(size_t)r * DD + 256 + t];
    float s  = v0 + v1;
    float sq = v0 * v0 + v1 * v1;

    __shared__ float rs[8], rq[8];
    __shared__ float mu_s, rstd_s;
    #pragma unroll
    for (int o = 16; o > 0; o >>= 1) {
        s  += __shfl_xor_sync(0xffffffffu, s, o);
        sq += __shfl_xor_sync(0xffffffffu, sq, o);
    }
    if (lane == 0) { rs[warp] = s; rq[warp] = sq; }
    __syncthreads();
    if (t == 0) {
        float S = 0.f, Q2 = 0.f;
        #pragma unroll
        for (int w = 0; w < 8; w++) { S += rs[w]; Q2 += rq[w]; }
        float mu  = S / 512.f;
        float var = Q2 / 512.f - mu * mu;
        mu_s = mu;
        rstd_s = rsqrtf(var + 1e-5f);
    }
    __syncthreads();
    float mu = mu_s, rstd = rstd_s;

    float y0 = (v0 - mu) * rstd * gamma[t]       + beta[t];
    float y1 = (v1 - mu) * rstd * gamma[256 + t] + beta[256 + t];
    out[(size_t)r * DD + t]       = fmaxf(y0, 0.f);
    out[(size_t)r * DD + 256 + t] = fmaxf(y1, 0.f);
}

// ---------------------------------------------------------------------------
extern "C" void kernel_launch(void* const* d_in, const int* in_sizes, int n_in,
                              void* d_out, int out_size)
{
    const float* x     = (const float*)d_in[0];
    const int*   adj   = (const int*)  d_in[1];
    const float* e     = (const float*)d_in[2];
    const float* Wq    = (const float*)d_in[3];
    const float* Wkv   = (const float*)d_in[4];
    const float* We    = (const float*)d_in[5];
    const float* Wf    = (const float*)d_in[6];
    const float* bf    = (const float*)d_in[7];
    const float* gamma = (const float*)d_in[8];
    const float* beta  = (const float*)d_in[9];
    float* out = (float*)d_out;

    float *pQ, *pKV, *pATTN, *pFFN;
    cudaGetSymbolAddress((void**)&pQ,    dQ);
    cudaGetSymbolAddress((void**)&pKV,   dKV);
    cudaGetSymbolAddress((void**)&pATTN, dATTN);
    cudaGetSymbolAddress((void**)&pFFN,  dFFN);

    // 1. Q = x@Wq, KV = x@Wkv
    gemm_f2<<<dim3(DD/64, BL/64, 2), 128>>>(x, Wq, pQ, Wkv, pKV, nullptr, DD, DD);
    // 2. g = We_h^T q_h
    g_kernel<<<dim3(BL/64, HH), 256>>>(We);
    // 3. S1 = Q_h @ KV_h^T
    s1_f2<<<dim3(BB*HH, 2), 256>>>();
    // 4. softmax + alpha-weighted e reduction (smem-trimmed, 5 blocks/SM)
    softmax4<<<BL, 256>>>(e, adj);
    // 5. attention output
    attn_f2<<<dim3(BB*HH, 2), 128>>>(We);
    // 6. FFN GEMM with bias
    gemm_f2<<<dim3(DD/64, BL/64, 1), 128>>>(pATTN, Wf, pFFN, nullptr, nullptr, bf, DD, DD);
    // 7. LayerNorm + ReLU
    ln_kernel<<<BL, 256>>>(gamma, beta, out);
}

// round 8
// speedup vs baseline: 1.1575x; 1.1509x over previous
#include <cuda_runtime.h>
#include <math.h>
#include <stdint.h>

#define BB 8
#define LL 128
#define DD 512
#define EE 64
#define HH 8
#define BL (BB*LL)   // 1024

typedef unsigned long long ull;

__device__ __forceinline__ void fma2(ull &acc, ull a, ull b) {
    asm("fma.rn.f32x2 %0, %1, %2, %0;" : "+l"(acc) : "l"(a), "l"(b));
}
__device__ __forceinline__ void add2(ull &a, ull b) {
    asm("add.rn.f32x2 %0, %0, %1;" : "+l"(a) : "l"(b));
}
__device__ __forceinline__ ull pack2(float x, float y) {
    ull r; asm("mov.b64 %0, {%1,%2};" : "=l"(r) : "f"(x), "f"(y)); return r;
}
__device__ __forceinline__ void unpack2(ull v, float &x, float &y) {
    asm("mov.b64 {%0,%1}, %2;" : "=f"(x), "=f"(y) : "l"(v));
}
__device__ __forceinline__ float fsum2(ull v) {
    float x, y; unpack2(v, x, y); return x + y;
}

// cp.async helpers (Ampere+, valid on plain sm_103)
__device__ __forceinline__ uint32_t smem_u32(const void* p) {
    uint32_t a;
    asm("{ .reg .u64 t; cvta.to.shared.u64 t, %1; cvt.u32.u64 %0, t; }" : "=r"(a) : "l"(p));
    return a;
}
__device__ __forceinline__ void cp16(uint32_t d, const void* s) {
    asm volatile("cp.async.ca.shared.global [%0], [%1], 16;" :: "r"(d), "l"(s));
}
__device__ __forceinline__ void cp_commit() {
    asm volatile("cp.async.commit_group;" ::: "memory");
}
template<int N> __device__ __forceinline__ void cp_wait() {
    asm volatile("cp.async.wait_group %0;" :: "n"(N) : "memory");
}

// Scratch
__device__ float dQ[BL*DD];
__device__ float dKV[BL*DD];
__device__ float dG[BL*HH*EE];           // [bq][h][e]
__device__ float dS1[BB*HH*LL*LL];       // [bh][q][k]
__device__ float dALPHA[BB*HH*LL*LL];    // [bh][q][k]
__device__ float dWsum[BB*HH*LL*EE];     // [bh][q][e]
__device__ float dATTN[BL*DD];
__device__ float dFFN[BL*DD];

// ---------------------------------------------------------------------------
// cp.async double-buffered f32x2 GEMM, n-pair accumulators (no B transpose).
// 64x64 tile, 128 threads, K-tile 32.  acc[i][j] = C[m0+ty*8+i][n0+tx*2+32j .. +1]
// ---------------------------------------------------------------------------
__global__ __launch_bounds__(128) void gemm_ca(
    const float* __restrict__ A,
    const float* __restrict__ B0, float* __restrict__ C0,
    const float* __restrict__ B1, float* __restrict__ C1,
    const float* __restrict__ bias, int K, int N)
{
    __shared__ float As[2][64*36];   // [m][kk], 16B-aligned rows (144B)
    __shared__ float Bs[2][32*64];   // [kk][n], natural layout

    const float* Bm = blockIdx.z ? B1 : B0;
    float*       Cm = blockIdx.z ? C1 : C0;

    const int t  = threadIdx.x;
    const int tx = t & 15, ty = t >> 4;           // ty 0..7
    const int m0 = blockIdx.y * 64, n0 = blockIdx.x * 64;

    const uint32_t asb = smem_u32(&As[0][0]);
    const uint32_t bsb = smem_u32(&Bs[0][0]);

    ull acc[8][2] = {};

    // --- tile issue (cp.async) ---
    // A: 512 float4; B: 512 float4; 4 each per thread
    #define ISSUE_TILE(buf, k0) do {                                            \
        _Pragma("unroll")                                                       \
        for (int r = 0; r < 4; r++) {                                           \
            int idx = t + r * 128;                                              \
            int m = idx >> 3, k4 = (idx & 7) << 2;                              \
            cp16(asb + (buf) * 9216u + (uint32_t)(m * 36 + k4) * 4u,            \
                 A + (size_t)(m0 + m) * K + (k0) + k4);                         \
        }                                                                       \
        _Pragma("unroll")                                                       \
        for (int r = 0; r < 4; r++) {                                           \
            int idx = t + r * 128;                                              \
            int kk = idx >> 4, n4 = (idx & 15) << 2;                            \
            cp16(bsb + (buf) * 8192u + (uint32_t)(kk * 64 + n4) * 4u,           \
                 Bm + (size_t)((k0) + kk) * N + n0 + n4);                       \
        }                                                                       \
        cp_commit();                                                            \
    } while (0)

    ISSUE_TILE(0, 0);

    const int NT = K / 32;
    int buf = 0;
    for (int kt = 0; kt < NT; kt++) {
        if (kt + 1 < NT) { ISSUE_TILE(buf ^ 1, (kt + 1) * 32); cp_wait<1>(); }
        else             { cp_wait<0>(); }
        __syncthreads();

        #pragma unroll 4
        for (int kk = 0; kk < 32; kk += 2) {
            ull bp00 = *(const ull*)&Bs[buf][kk * 64 + tx * 2];
            ull bp01 = *(const ull*)&Bs[buf][kk * 64 + tx * 2 + 32];
            ull bp10 = *(const ull*)&Bs[buf][(kk + 1) * 64 + tx * 2];
            ull bp11 = *(const ull*)&Bs[buf][(kk + 1) * 64 + tx * 2 + 32];
            #pragma unroll
            for (int i = 0; i < 8; i++) {
                float2 af = *(const float2*)&As[buf][(ty * 8 + i) * 36 + kk];
                ull ad0 = pack2(af.x, af.x);
                ull ad1 = pack2(af.y, af.y);
                fma2(acc[i][0], ad0, bp00);
                fma2(acc[i][1], ad0, bp01);
                fma2(acc[i][0], ad1, bp10);
                fma2(acc[i][1], ad1, bp11);
            }
        }
        __syncthreads();
        buf ^= 1;
    }
    #undef ISSUE_TILE

    #pragma unroll
    for (int i = 0; i < 8; i++) {
        int m = m0 + ty * 8 + i;
        float x0, x1, y0, y1;
        unpack2(acc[i][0], x0, x1);
        unpack2(acc[i][1], y0, y1);
        int nA = n0 + tx * 2, nB = nA + 32;
        if (bias) {
            x0 += bias[nA]; x1 += bias[nA + 1];
            y0 += bias[nB]; y1 += bias[nB + 1];
        }
        *(float2*)(Cm + (size_t)m * N + nA) = make_float2(x0, x1);
        *(float2*)(Cm + (size_t)m * N + nB) = make_float2(y0, y1);
    }
}

// ---------------------------------------------------------------------------
// attn as cp.async GEMM: C = [alpha | Wsum] @ [KV_h ; We_h], K=192, tile 64x64
// grid (64, 2): bh, mh
// ---------------------------------------------------------------------------
__global__ __launch_bounds__(128) void attn_ca(const float* __restrict__ We)
{
    __shared__ float As[2][64*36];
    __shared__ float Bs[2][32*64];

    const int bh = blockIdx.x, mh = blockIdx.y;
    const int b  = bh >> 3, h = bh & 7;
    const int t  = threadIdx.x;
    const int tx = t & 15, ty = t >> 4;

    const uint32_t asb = smem_u32(&As[0][0]);
    const uint32_t bsb = smem_u32(&Bs[0][0]);

    ull acc[8][2] = {};

    #define ISSUE_ATTN(buf, k0) do {                                            \
        _Pragma("unroll")                                                       \
        for (int r = 0; r < 4; r++) {                                           \
            int idx = t + r * 128;                                              \
            int m = idx >> 3, k4 = (idx & 7) << 2;                              \
            size_t row = (size_t)bh * LL + mh * 64 + m;                         \
            const float* src = ((k0) < 128)                                     \
                ? (dALPHA + row * LL + (k0) + k4)                               \
                : (dWsum  + row * EE + ((k0) - 128) + k4);                      \
            cp16(asb + (buf) * 9216u + (uint32_t)(m * 36 + k4) * 4u, src);      \
        }                                                                       \
        _Pragma("unroll")                                                       \
        for (int r = 0; r < 4; r++) {                                           \
            int idx = t + r * 128;                                              \
            int kk = idx >> 4, n4 = (idx & 15) << 2;                            \
            int kg = (k0) + kk;                                                 \
            const float* src = (kg < 128)                                       \
                ? (dKV + (size_t)(b * LL + kg) * DD + h * 64 + n4)              \
                : (We  + (size_t)(kg - 128) * DD + h * 64 + n4);                \
            cp16(bsb + (buf) * 8192u + (uint32_t)(kk * 64 + n4) * 4u, src);     \
        }                                                                       \
        cp_commit();                                                            \
    } while (0)

    ISSUE_ATTN(0, 0);

    const int NT = 6;   // K = 192
    int buf = 0;
    for (int kt = 0; kt < NT; kt++) {
        if (kt + 1 < NT) { ISSUE_ATTN(buf ^ 1, (kt + 1) * 32); cp_wait<1>(); }
        else             { cp_wait<0>(); }
        __syncthreads();

        #pragma unroll 4
        for (int kk = 0; kk < 32; kk += 2) {
            ull bp00 = *(const ull*)&Bs[buf][kk * 64 + tx * 2];
            ull bp01 = *(const ull*)&Bs[buf][kk * 64 + tx * 2 + 32];
            ull bp10 = *(const ull*)&Bs[buf][(kk + 1) * 64 + tx * 2];
            ull bp11 = *(const ull*)&Bs[buf][(kk + 1) * 64 + tx * 2 + 32];
            #pragma unroll
            for (int i = 0; i < 8; i++) {
                float2 af = *(const float2*)&As[buf][(ty * 8 + i) * 36 + kk];
                ull ad0 = pack2(af.x, af.x);
                ull ad1 = pack2(af.y, af.y);
                fma2(acc[i][0], ad0, bp00);
                fma2(acc[i][1], ad0, bp01);
                fma2(acc[i][0], ad1, bp10);
                fma2(acc[i][1], ad1, bp11);
            }
        }
        __syncthreads();
        buf ^= 1;
    }
    #undef ISSUE_ATTN

    #pragma unroll
    for (int i = 0; i < 8; i++) {
        int m = mh * 64 + ty * 8 + i;
        float* crow = dATTN + ((size_t)(b * LL) + m) * DD + h * 64;
        float x0, x1, y0, y1;
        unpack2(acc[i][0], x0, x1);
        unpack2(acc[i][1], y0, y1);
        *(float2*)(crow + tx * 2)      = make_float2(x0, x1);
        *(float2*)(crow + tx * 2 + 32) = make_float2(y0, y1);
    }
}

// ---------------------------------------------------------------------------
// g[bq][h][e] = sum_c Q[bq, h*64+c] * We[e, h*64+c]
// ---------------------------------------------------------------------------
__global__ __launch_bounds__(256) void g_kernel(const float* __restrict__ We)
{
    __shared__ float Qs[64 * 65];
    __shared__ float Ws[64 * 65];

    const int t  = threadIdx.x;
    const int tx = t & 15, ty = t >> 4;
    const int r0 = blockIdx.x * 64;
    const int h  = blockIdx.y;

    #pragma unroll
    for (int r = 0; r < 4; r++) {
        int idx = t + r * 256;
        int m   = idx >> 4;
        int c4  = (idx & 15) << 2;
        float4 q = *(const float4*)(dQ + (size_t)(r0 + m) * DD + h * 64 + c4);
        Qs[m * 65 + c4 + 0] = q.x; Qs[m * 65 + c4 + 1] = q.y;
        Qs[m * 65 + c4 + 2] = q.z; Qs[m * 65 + c4 + 3] = q.w;
        float4 w = *(const float4*)(We + (size_t)m * DD + h * 64 + c4);
        Ws[m * 65 + c4 + 0] = w.x; Ws[m * 65 + c4 + 1] = w.y;
        Ws[m * 65 + c4 + 2] = w.z; Ws[m * 65 + c4 + 3] = w.w;
    }
    __syncthreads();

    float acc[4][4] = {};
    #pragma unroll
    for (int c = 0; c < 64; c++) {
        float a[4], b[4];
        #pragma unroll
        for (int i = 0; i < 4; i++) a[i] = Qs[(ty + 16 * i) * 65 + c];
        #pragma unroll
        for (int j = 0; j < 4; j++) b[j] = Ws[(tx + 16 * j) * 65 + c];
        #pragma unroll
        for (int i = 0; i < 4; i++)
            #pragma unroll
            for (int j = 0; j < 4; j++)
                acc[i][j] += a[i] * b[j];
    }

    #pragma unroll
    for (int i = 0; i < 4; i++) {
        int m = r0 + ty + 16 * i;
        #pragma unroll
        for (int j = 0; j < 4; j++)
            dG[((size_t)m * HH + h) * EE + tx + 16 * j] = acc[i][j];
    }
}

// ---------------------------------------------------------------------------
// S1: 64m x 128n per block, grid (64,2), 256 threads, frag 4m x 8n, f32x2
// ---------------------------------------------------------------------------
__global__ __launch_bounds__(256) void s1_f2()
{
    __shared__ float Qs[64 * 34];
    __shared__ float Ks[128 * 34];

    const int bh = blockIdx.x, mh = blockIdx.y;
    const int b  = bh >> 3, h = bh & 7;
    const int t  = threadIdx.x;
    const int tx = t & 15, ty = t >> 4;

    ull acc[4][8] = {};

    for (int c0 = 0; c0 < 64; c0 += 32) {
        #pragma unroll
        for (int r = 0; r < 2; r++) {
            int idx = t + r * 256;
            int m   = idx >> 3;
            int c4  = (idx & 7) << 2;
            float4 v = *(const float4*)(dQ + (size_t)(b * LL + mh * 64 + m) * DD + h * 64 + c0 + c4);
            *(float2*)(Qs + m * 34 + c4)     = make_float2(v.x, v.y);
            *(float2*)(Qs + m * 34 + c4 + 2) = make_float2(v.z, v.w);
        }
        #pragma unroll
        for (int r = 0; r < 4; r++) {
            int idx = t + r * 256;
            int n   = idx >> 3;
            int c4  = (idx & 7) << 2;
            float4 v = *(const float4*)(dKV + (size_t)(b * LL + n) * DD + h * 64 + c0 + c4);
            *(float2*)(Ks + n * 34 + c4)     = make_float2(v.x, v.y);
            *(float2*)(Ks + n * 34 + c4 + 2) = make_float2(v.z, v.w);
        }
        __syncthreads();

        #pragma unroll
        for (int cc = 0; cc < 32; cc += 2) {
            ull a[4], b2[8];
            #pragma unroll
            for (int i = 0; i < 4; i++) a[i]  = *(const ull*)(Qs + (ty * 4 + i) * 34 + cc);
            #pragma unroll
            for (int j = 0; j < 8; j++) b2[j] = *(const ull*)(Ks + (tx + 16 * j) * 34 + cc);
            #pragma unroll
            for (int i = 0; i < 4; i++)
                #pragma unroll
                for (int j = 0; j < 8; j++)
                    fma2(acc[i][j], a[i], b2[j]);
        }
        __syncthreads();
    }

    #pragma unroll
    for (int i = 0; i < 4; i++) {
        int m = mh * 64 + ty * 4 + i;
        #pragma unroll
        for (int j = 0; j < 8; j++)
            dS1[((size_t)bh * LL + m) * LL + tx + 16 * j] = fsum2(acc[i][j]);
    }
}

// ---------------------------------------------------------------------------
// Softmax v4 (proven): 256 threads per (b,q), all 8 heads, ~41.2KB smem.
// ---------------------------------------------------------------------------
__global__ __launch_bounds__(256, 5) void softmax4(
    const float* __restrict__ eptr, const int* __restrict__ adj)
{
    __shared__ float es[128 * 68];
    __shared__ float gT[512];
    __shared__ float aT[1024];
    __shared__ float redM[32];
    __shared__ float redS[32];

    const int bq = blockIdx.x;
    const int b  = bq >> 7, q = bq & 127;
    const int t  = threadIdx.x;
    const int lane = t & 31, warp = t >> 5;

    const float* erow = eptr + (size_t)bq * LL * EE;
    #pragma unroll
    for (int r = 0; r < 8; r++) {
        int idx = t + r * 256;
        int k   = idx >> 4;
        int j4  = (idx & 15) << 2;
        float4 v = *(const float4*)(erow + k * EE + j4);
        *(float4*)(es + k * 68 + j4) = v;
    }
    #pragma unroll
    for (int i0 = 0; i0 < 2; i0++) {
        int i = t + i0 * 256;
        int h = i >> 6, j = i & 63;
        gT[j * 8 + h] = dG[(size_t)bq * 512 + i];
    }
    __syncthreads();

    const int k  = t & 127;
    const int jh = t >> 7;
    ull acc2[4] = {0, 0, 0, 0};
    #pragma unroll
    for (int j4 = 0; j4 < 8; j4++) {
        float4 ev4 = *(const float4*)(es + k * 68 + jh * 32 + j4 * 4);
        float evv[4] = {ev4.x, ev4.y, ev4.z, ev4.w};
        #pragma unroll
        for (int c = 0; c < 4; c++) {
            int j = jh * 32 + j4 * 4 + c;
            ull ed = pack2(evv[c], evv[c]);
            ulonglong2 g01 = *(const ulonglong2*)(gT + j * 8);
            ulonglong2 g23 = *(const ulonglong2*)(gT + j * 8 + 4);
            fma2(acc2[0], ed, g01.x); fma2(acc2[1], ed, g01.y);
            fma2(acc2[2], ed, g23.x); fma2(acc2[3], ed, g23.y);
        }
    }
    if (jh == 1) {
        *(ulonglong2*)(aT + k * 8)     = make_ulonglong2(acc2[0], acc2[1]);
        *(ulonglong2*)(aT + k * 8 + 4) = make_ulonglong2(acc2[2], acc2[3]);
    }
    __syncthreads();

    float sv[8];
    if (t < 128) {
        ulonglong2 p01 = *(const ulonglong2*)(aT + k * 8);
        ulonglong2 p23 = *(const ulonglong2*)(aT + k * 8 + 4);
        add2(acc2[0], p01.x); add2(acc2[1], p01.y);
        add2(acc2[2], p23.x); add2(acc2[3], p23.y);
        unpack2(acc2[0], sv[0], sv[1]);
        unpack2(acc2[1], sv[2], sv[3]);
        unpack2(acc2[2], sv[4], sv[5]);
        unpack2(acc2[3], sv[6], sv[7]);
        const int adjv = adj[(size_t)bq * LL + k];
        #pragma unroll
        for (int h = 0; h < HH; h++) {
            float s = (dS1[(((size_t)(b * HH + h)) * LL + q) * LL + k] + sv[h]) * 0.125f;
            s = (s > 0.f) ? s : 0.2f * s;
            if (adjv == 0) s = -1e9f;
            sv[h] = s;
        }
        #pragma unroll
        for (int h = 0; h < HH; h++) {
            float m = sv[h];
            #pragma unroll
            for (int o = 16; o > 0; o >>= 1) m = fmaxf(m, __shfl_xor_sync(0xffffffffu, m, o));
            if (lane == 0) redM[warp * 8 + h] = m;
        }
    }
    __syncthreads();

    float p[8];
    if (t < 128) {
        #pragma unroll
        for (int h = 0; h < HH; h++) {
            float mx = fmaxf(fmaxf(redM[h], redM[8 + h]), fmaxf(redM[16 + h], redM[24 + h]));
            p[h] = __expf(sv[h] - mx);
        }
        #pragma unroll
        for (int h = 0; h < HH; h++) {
            float s = p[h];
            #pragma unroll
            for (int o = 16; o > 0; o >>= 1) s += __shfl_xor_sync(0xffffffffu, s, o);
            if (lane == 0) redS[warp * 8 + h] = s;
        }
    }
    __syncthreads();

    if (t < 128) {
        float al[8];
        #pragma unroll
        for (int h = 0; h < HH; h++) {
            float tot = redS[h] + redS[8 + h] + redS[16 + h] + redS[24 + h];
            al[h] = p[h] / tot;
            dALPHA[(((size_t)(b * HH + h)) * LL + q) * LL + k] = al[h];
        }
        *(float4*)(aT + k * 8)     = make_float4(al[0], al[1], al[2], al[3]);
        *(float4*)(aT + k * 8 + 4) = make_float4(al[4], al[5], al[6], al[7]);
    }
    __syncthreads();

    const int ei = t & 63, qt = t >> 6;
    ull w2[4] = {0, 0, 0, 0};
    #pragma unroll 8
    for (int kk = 0; kk < 32; kk++) {
        int kq = qt * 32 + kk;
        float ev = es[kq * 68 + ei];
        ull ed = pack2(ev, ev);
        ulonglong2 a01 = *(const ulonglong2*)(aT + kq * 8);
        ulonglong2 a23 = *(const ulonglong2*)(aT + kq * 8 + 4);
        fma2(w2[0], ed, a01.x); fma2(w2[1], ed, a01.y);
        fma2(w2[2], ed, a23.x); fma2(w2[3], ed, a23.y);
    }
    __syncthreads();

    if (qt == 1) {
        *(ulonglong2*)(aT + ei * 8)       = make_ulonglong2(w2[0], w2[1]);
        *(ulonglong2*)(aT + ei * 8 + 4)   = make_ulonglong2(w2[2], w2[3]);
    } else if (qt == 2) {
        *(ulonglong2*)(aT + 512 + ei * 8)     = make_ulonglong2(w2[0], w2[1]);
        *(ulonglong2*)(aT + 512 + ei * 8 + 4) = make_ulonglong2(w2[2], w2[3]);
    } else if (qt == 3) {
        *(ulonglong2*)(gT + ei * 8)       = make_ulonglong2(w2[0], w2[1]);
        *(ulonglong2*)(gT + ei * 8 + 4)   = make_ulonglong2(w2[2], w2[3]);
    }
    __syncthreads();

    if (qt == 0) {
        ulonglong2 s1a = *(const ulonglong2*)(aT + ei * 8);
        ulonglong2 s1b = *(const ulonglong2*)(aT + ei * 8 + 4);
        ulonglong2 s2a = *(const ulonglong2*)(aT + 512 + ei * 8);
        ulonglong2 s2b = *(const ulonglong2*)(aT + 512 + ei * 8 + 4);
        ulonglong2 s3a = *(const ulonglong2*)(gT + ei * 8);
        ulonglong2 s3b = *(const ulonglong2*)(gT + ei * 8 + 4);
        add2(w2[0], s1a.x); add2(w2[1], s1a.y); add2(w2[2], s1b.x); add2(w2[3], s1b.y);
        add2(w2[0], s2a.x); add2(w2[1], s2a.y); add2(w2[2], s2b.x); add2(w2[3], s2b.y);
        add2(w2[0], s3a.x); add2(w2[1], s3a.y); add2(w2[2], s3b.x); add2(w2[3], s3b.y);
        float w[8];
        unpack2(w2[0], w[0], w[1]); unpack2(w2[1], w[2], w[3]);
        unpack2(w2[2], w[4], w[5]); unpack2(w2[3], w[6], w[7]);
        #pragma unroll
        for (int h = 0; h < HH; h++)
            dWsum[(((size_t)(b * HH + h)) * LL + q) * EE + ei] = w[h];
    }
}

// ---------------------------------------------------------------------------
// LayerNorm + ReLU per row of 512
// ---------------------------------------------------------------------------
__global__ __launch_bounds__(256) void ln_kernel(
    const float* __restrict__ gamma, const float* __restrict__ beta,
    float* __restrict__ out)
{
    const int r = blockIdx.x;
    const int t = threadIdx.x;
    const int lane = t & 31, warp = t >> 5;

    float v0 = dFFN[(size_t)r * DD + t];
    float v1 = dFFN[(size_t)r * DD + 256 + t];
    float s  = v0 + v1;
    float sq = v0 * v0 + v1 * v1;

    __shared__ float rs[8], rq[8];
    __shared__ float mu_s, rstd_s;
    #pragma unroll
    for (int o = 16; o > 0; o >>= 1) {
        s  += __shfl_xor_sync(0xffffffffu, s, o);
        sq += __shfl_xor_sync(0xffffffffu, sq, o);
    }
    if (lane == 0) { rs[warp] = s; rq[warp] = sq; }
    __syncthreads();
    if (t == 0) {
        float S = 0.f, Q2 = 0.f;
        #pragma unroll
        for (int w = 0; w < 8; w++) { S += rs[w]; Q2 += rq[w]; }
        float mu  = S / 512.f;
        float var = Q2 / 512.f - mu * mu;
        mu_s = mu;
        rstd_s = rsqrtf(var + 1e-5f);
    }
    __syncthreads();
    float mu = mu_s, rstd = rstd_s;

    float y0 = (v0 - mu) * rstd * gamma[t]       + beta[t];
    float y1 = (v1 - mu) * rstd * gamma[256 + t] + beta[256 + t];
    out[(size_t)r * DD + t]       = fmaxf(y0, 0.f);
    out[(size_t)r * DD + 256 + t] = fmaxf(y1, 0.f);
}

// ---------------------------------------------------------------------------
extern "C" void kernel_launch(void* const* d_in, const int* in_sizes, int n_in,
                              void* d_out, int out_size)
{
    const float* x     = (const float*)d_in[0];
    const int*   adj   = (const int*)  d_in[1];
    const float* e     = (const float*)d_in[2];
    const float* Wq    = (const float*)d_in[3];
    const float* Wkv   = (const float*)d_in[4];
    const float* We    = (const float*)d_in[5];
    const float* Wf    = (const float*)d_in[6];
    const float* bf    = (const float*)d_in[7];
    const float* gamma = (const float*)d_in[8];
    const float* beta  = (const float*)d_in[9];
    float* out = (float*)d_out;

    float *pQ, *pKV, *pATTN, *pFFN;
    cudaGetSymbolAddress((void**)&pQ,    dQ);
    cudaGetSymbolAddress((void**)&pKV,   dKV);
    cudaGetSymbolAddress((void**)&pATTN, dATTN);
    cudaGetSymbolAddress((void**)&pFFN,  dFFN);

    // 1. Q = x@Wq, KV = x@Wkv (cp.async double-buffered)
    gemm_ca<<<dim3(DD/64, BL/64, 2), 128>>>(x, Wq, pQ, Wkv, pKV, nullptr, DD, DD);
    // 2. g = We_h^T q_h
    g_kernel<<<dim3(BL/64, HH), 256>>>(We);
    // 3. S1 = Q_h @ KV_h^T
    s1_f2<<<dim3(BB*HH, 2), 256>>>();
    // 4. softmax + alpha-weighted e reduction
    softmax4<<<BL, 256>>>(e, adj);
    // 5. attention output (cp.async GEMM)
    attn_ca<<<dim3(BB*HH, 2), 128>>>(We);
    // 6. FFN GEMM with bias (cp.async)
    gemm_ca<<<dim3(DD/64, BL/64, 1), 128>>>(pATTN, Wf, pFFN, nullptr, nullptr, bf, DD, DD);
    // 7. LayerNorm + ReLU
    ln_kernel<<<BL, 256>>>(gamma, beta, out);
}

// round 9
// speedup vs baseline: 1.1803x; 1.0197x over previous
#include <cuda_runtime.h>
#include <math.h>
#include <stdint.h>

#define BB 8
#define LL 128
#define DD 512
#define EE 64
#define HH 8
#define BL (BB*LL)   // 1024

typedef unsigned long long ull;

__device__ __forceinline__ void fma2(ull &acc, ull a, ull b) {
    asm("fma.rn.f32x2 %0, %1, %2, %0;" : "+l"(acc) : "l"(a), "l"(b));
}
__device__ __forceinline__ void add2(ull &a, ull b) {
    asm("add.rn.f32x2 %0, %0, %1;" : "+l"(a) : "l"(b));
}
__device__ __forceinline__ ull pack2(float x, float y) {
    ull r; asm("mov.b64 %0, {%1,%2};" : "=l"(r) : "f"(x), "f"(y)); return r;
}
__device__ __forceinline__ void unpack2(ull v, float &x, float &y) {
    asm("mov.b64 {%0,%1}, %2;" : "=f"(x), "=f"(y) : "l"(v));
}
__device__ __forceinline__ float fsum2(ull v) {
    float x, y; unpack2(v, x, y); return x + y;
}

// cp.async helpers
__device__ __forceinline__ uint32_t smem_u32(const void* p) {
    uint32_t a;
    asm("{ .reg .u64 t; cvta.to.shared.u64 t, %1; cvt.u32.u64 %0, t; }" : "=r"(a) : "l"(p));
    return a;
}
__device__ __forceinline__ void cp16(uint32_t d, const void* s) {
    asm volatile("cp.async.ca.shared.global [%0], [%1], 16;" :: "r"(d), "l"(s));
}
__device__ __forceinline__ void cp_commit() {
    asm volatile("cp.async.commit_group;" ::: "memory");
}
template<int N> __device__ __forceinline__ void cp_wait() {
    asm volatile("cp.async.wait_group %0;" :: "n"(N) : "memory");
}

// Scratch
__device__ float dQ[BL*DD];
__device__ float dKV[BL*DD];
__device__ float dG[BL*HH*EE];           // [bq][h][e]
__device__ float dS1[BB*HH*LL*LL];       // [bh][q][k]
__device__ float dALPHA[BB*HH*LL*LL];    // [bh][q][k]
__device__ float dWsum[BB*HH*LL*EE];     // [bh][q][e]
__device__ float dATTN[BL*DD];
__device__ float dFFN[BL*DD];

// ---------------------------------------------------------------------------
// cp.async double-buffered f32x2 GEMM, n-pair accumulators (R8, proven).
// ---------------------------------------------------------------------------
__global__ __launch_bounds__(128) void gemm_ca(
    const float* __restrict__ A,
    const float* __restrict__ B0, float* __restrict__ C0,
    const float* __restrict__ B1, float* __restrict__ C1,
    const float* __restrict__ bias, int K, int N)
{
    __shared__ float As[2][64*36];
    __shared__ float Bs[2][32*64];

    const float* Bm = blockIdx.z ? B1 : B0;
    float*       Cm = blockIdx.z ? C1 : C0;

    const int t  = threadIdx.x;
    const int tx = t & 15, ty = t >> 4;
    const int m0 = blockIdx.y * 64, n0 = blockIdx.x * 64;

    const uint32_t asb = smem_u32(&As[0][0]);
    const uint32_t bsb = smem_u32(&Bs[0][0]);

    ull acc[8][2] = {};

    #define ISSUE_TILE(buf, k0) do {                                            \
        _Pragma("unroll")                                                       \
        for (int r = 0; r < 4; r++) {                                           \
            int idx = t + r * 128;                                              \
            int m = idx >> 3, k4 = (idx & 7) << 2;                              \
            cp16(asb + (buf) * 9216u + (uint32_t)(m * 36 + k4) * 4u,            \
                 A + (size_t)(m0 + m) * K + (k0) + k4);                         \
        }                                                                       \
        _Pragma("unroll")                                                       \
        for (int r = 0; r < 4; r++) {                                           \
            int idx = t + r * 128;                                              \
            int kk = idx >> 4, n4 = (idx & 15) << 2;                            \
            cp16(bsb + (buf) * 8192u + (uint32_t)(kk * 64 + n4) * 4u,           \
                 Bm + (size_t)((k0) + kk) * N + n0 + n4);                       \
        }                                                                       \
        cp_commit();                                                            \
    } while (0)

    ISSUE_TILE(0, 0);

    const int NT = K / 32;
    int buf = 0;
    for (int kt = 0; kt < NT; kt++) {
        if (kt + 1 < NT) { ISSUE_TILE(buf ^ 1, (kt + 1) * 32); cp_wait<1>(); }
        else             { cp_wait<0>(); }
        __syncthreads();

        #pragma unroll 4
        for (int kk = 0; kk < 32; kk += 2) {
            ull bp00 = *(const ull*)&Bs[buf][kk * 64 + tx * 2];
            ull bp01 = *(const ull*)&Bs[buf][kk * 64 + tx * 2 + 32];
            ull bp10 = *(const ull*)&Bs[buf][(kk + 1) * 64 + tx * 2];
            ull bp11 = *(const ull*)&Bs[buf][(kk + 1) * 64 + tx * 2 + 32];
            #pragma unroll
            for (int i = 0; i < 8; i++) {
                float2 af = *(const float2*)&As[buf][(ty * 8 + i) * 36 + kk];
                ull ad0 = pack2(af.x, af.x);
                ull ad1 = pack2(af.y, af.y);
                fma2(acc[i][0], ad0, bp00);
                fma2(acc[i][1], ad0, bp01);
                fma2(acc[i][0], ad1, bp10);
                fma2(acc[i][1], ad1, bp11);
            }
        }
        __syncthreads();
        buf ^= 1;
    }
    #undef ISSUE_TILE

    #pragma unroll
    for (int i = 0; i < 8; i++) {
        int m = m0 + ty * 8 + i;
        float x0, x1, y0, y1;
        unpack2(acc[i][0], x0, x1);
        unpack2(acc[i][1], y0, y1);
        int nA = n0 + tx * 2, nB = nA + 32;
        if (bias) {
            x0 += bias[nA]; x1 += bias[nA + 1];
            y0 += bias[nB]; y1 += bias[nB + 1];
        }
        *(float2*)(Cm + (size_t)m * N + nA) = make_float2(x0, x1);
        *(float2*)(Cm + (size_t)m * N + nB) = make_float2(y0, y1);
    }
}

// ---------------------------------------------------------------------------
// attn cp.async GEMM (R8, proven): C = [alpha | Wsum] @ [KV_h ; We_h], K=192
// ---------------------------------------------------------------------------
__global__ __launch_bounds__(128) void attn_ca(const float* __restrict__ We)
{
    __shared__ float As[2][64*36];
    __shared__ float Bs[2][32*64];

    const int bh = blockIdx.x, mh = blockIdx.y;
    const int b  = bh >> 3, h = bh & 7;
    const int t  = threadIdx.x;
    const int tx = t & 15, ty = t >> 4;

    const uint32_t asb = smem_u32(&As[0][0]);
    const uint32_t bsb = smem_u32(&Bs[0][0]);

    ull acc[8][2] = {};

    #define ISSUE_ATTN(buf, k0) do {                                            \
        _Pragma("unroll")                                                       \
        for (int r = 0; r < 4; r++) {                                           \
            int idx = t + r * 128;                                              \
            int m = idx >> 3, k4 = (idx & 7) << 2;                              \
            size_t row = (size_t)bh * LL + mh * 64 + m;                         \
            const float* src = ((k0) < 128)                                     \
                ? (dALPHA + row * LL + (k0) + k4)                               \
                : (dWsum  + row * EE + ((k0) - 128) + k4);                      \
            cp16(asb + (buf) * 9216u + (uint32_t)(m * 36 + k4) * 4u, src);      \
        }                                                                       \
        _Pragma("unroll")                                                       \
        for (int r = 0; r < 4; r++) {                                           \
            int idx = t + r * 128;                                              \
            int kk = idx >> 4, n4 = (idx & 15) << 2;                            \
            int kg = (k0) + kk;                                                 \
            const float* src = (kg < 128)                                       \
                ? (dKV + (size_t)(b * LL + kg) * DD + h * 64 + n4)              \
                : (We  + (size_t)(kg - 128) * DD + h * 64 + n4);                \
            cp16(bsb + (buf) * 8192u + (uint32_t)(kk * 64 + n4) * 4u, src);     \
        }                                                                       \
        cp_commit();                                                            \
    } while (0)

    ISSUE_ATTN(0, 0);

    const int NT = 6;
    int buf = 0;
    for (int kt = 0; kt < NT; kt++) {
        if (kt + 1 < NT) { ISSUE_ATTN(buf ^ 1, (kt + 1) * 32); cp_wait<1>(); }
        else             { cp_wait<0>(); }
        __syncthreads();

        #pragma unroll 4
        for (int kk = 0; kk < 32; kk += 2) {
            ull bp00 = *(const ull*)&Bs[buf][kk * 64 + tx * 2];
            ull bp01 = *(const ull*)&Bs[buf][kk * 64 + tx * 2 + 32];
            ull bp10 = *(const ull*)&Bs[buf][(kk + 1) * 64 + tx * 2];
            ull bp11 = *(const ull*)&Bs[buf][(kk + 1) * 64 + tx * 2 + 32];
            #pragma unroll
            for (int i = 0; i < 8; i++) {
                float2 af = *(const float2*)&As[buf][(ty * 8 + i) * 36 + kk];
                ull ad0 = pack2(af.x, af.x);
                ull ad1 = pack2(af.y, af.y);
                fma2(acc[i][0], ad0, bp00);
                fma2(acc[i][1], ad0, bp01);
                fma2(acc[i][0], ad1, bp10);
                fma2(acc[i][1], ad1, bp11);
            }
        }
        __syncthreads();
        buf ^= 1;
    }
    #undef ISSUE_ATTN

    #pragma unroll
    for (int i = 0; i < 8; i++) {
        int m = mh * 64 + ty * 8 + i;
        float* crow = dATTN + ((size_t)(b * LL) + m) * DD + h * 64;
        float x0, x1, y0, y1;
        unpack2(acc[i][0], x0, x1);
        unpack2(acc[i][1], y0, y1);
        *(float2*)(crow + tx * 2)      = make_float2(x0, x1);
        *(float2*)(crow + tx * 2 + 32) = make_float2(y0, y1);
    }
}

// ---------------------------------------------------------------------------
// Merged s1 + g kernel: 256 blocks x 256 threads, shared smem pool.
//   bx <  128 : S1 = Q_h @ KV_h^T  (bh = bx>>1, mh = bx&1)
//   bx >= 128 : g  = Q_h @ We_h^T  (idx = bx-128: r0 = (idx>>3)*64, h = idx&7)
// ---------------------------------------------------------------------------
__global__ __launch_bounds__(256) void s1g_kernel(const float* __restrict__ We)
{
    __shared__ float pool[8320];   // max(6528 s1, 8320 g) floats

    const int bx = blockIdx.x;
    const int t  = threadIdx.x;
    const int tx = t & 15, ty = t >> 4;

    if (bx < 128) {
        // ---------------- s1 ----------------
        float* Qs = pool;            // [64][34]
        float* Ks = pool + 2176;     // [128][34]
        const int bh = bx >> 1, mh = bx & 1;
        const int b  = bh >> 3, h = bh & 7;

        ull acc[4][8] = {};

        for (int c0 = 0; c0 < 64; c0 += 32) {
            #pragma unroll
            for (int r = 0; r < 2; r++) {
                int idx = t + r * 256;
                int m   = idx >> 3;
                int c4  = (idx & 7) << 2;
                float4 v = *(const float4*)(dQ + (size_t)(b * LL + mh * 64 + m) * DD + h * 64 + c0 + c4);
                *(float2*)(Qs + m * 34 + c4)     = make_float2(v.x, v.y);
                *(float2*)(Qs + m * 34 + c4 + 2) = make_float2(v.z, v.w);
            }
            #pragma unroll
            for (int r = 0; r < 4; r++) {
                int idx = t + r * 256;
                int n   = idx >> 3;
                int c4  = (idx & 7) << 2;
                float4 v = *(const float4*)(dKV + (size_t)(b * LL + n) * DD + h * 64 + c0 + c4);
                *(float2*)(Ks + n * 34 + c4)     = make_float2(v.x, v.y);
                *(float2*)(Ks + n * 34 + c4 + 2) = make_float2(v.z, v.w);
            }
            __syncthreads();

            #pragma unroll
            for (int cc = 0; cc < 32; cc += 2) {
                ull a[4], b2[8];
                #pragma unroll
                for (int i = 0; i < 4; i++) a[i]  = *(const ull*)(Qs + (ty * 4 + i) * 34 + cc);
                #pragma unroll
                for (int j = 0; j < 8; j++) b2[j] = *(const ull*)(Ks + (tx + 16 * j) * 34 + cc);
                #pragma unroll
                for (int i = 0; i < 4; i++)
                    #pragma unroll
                    for (int j = 0; j < 8; j++)
                        fma2(acc[i][j], a[i], b2[j]);
            }
            __syncthreads();
        }

        #pragma unroll
        for (int i = 0; i < 4; i++) {
            int m = mh * 64 + ty * 4 + i;
            #pragma unroll
            for (int j = 0; j < 8; j++)
                dS1[((size_t)bh * LL + m) * LL + tx + 16 * j] = fsum2(acc[i][j]);
        }
    } else {
        // ---------------- g ----------------
        float* Qs = pool;            // [64][65]
        float* Ws = pool + 4160;     // [64][65]
        const int idx0 = bx - 128;
        const int r0 = (idx0 >> 3) * 64;
        const int h  = idx0 & 7;

        #pragma unroll
        for (int r = 0; r < 4; r++) {
            int idx = t + r * 256;
            int m   = idx >> 4;
            int c4  = (idx & 15) << 2;
            float4 q = *(const float4*)(dQ + (size_t)(r0 + m) * DD + h * 64 + c4);
            Qs[m * 65 + c4 + 0] = q.x; Qs[m * 65 + c4 + 1] = q.y;
            Qs[m * 65 + c4 + 2] = q.z; Qs[m * 65 + c4 + 3] = q.w;
            float4 w = *(const float4*)(We + (size_t)m * DD + h * 64 + c4);
            Ws[m * 65 + c4 + 0] = w.x; Ws[m * 65 + c4 + 1] = w.y;
            Ws[m * 65 + c4 + 2] = w.z; Ws[m * 65 + c4 + 3] = w.w;
        }
        __syncthreads();

        float acc[4][4] = {};
        #pragma unroll
        for (int c = 0; c < 64; c++) {
            float a[4], b[4];
            #pragma unroll
            for (int i = 0; i < 4; i++) a[i] = Qs[(ty + 16 * i) * 65 + c];
            #pragma unroll
            for (int j = 0; j < 4; j++) b[j] = Ws[(tx + 16 * j) * 65 + c];
            #pragma unroll
            for (int i = 0; i < 4; i++)
                #pragma unroll
                for (int j = 0; j < 4; j++)
                    acc[i][j] += a[i] * b[j];
        }

        #pragma unroll
        for (int i = 0; i < 4; i++) {
            int m = r0 + ty + 16 * i;
            #pragma unroll
            for (int j = 0; j < 4; j++)
                dG[((size_t)m * HH + h) * EE + tx + 16 * j] = acc[i][j];
        }
    }
}

// ---------------------------------------------------------------------------
// Softmax v5: cp.async streaming of es (34KB) + dS1 slab (4KB) into smem,
// overlapped with gT transpose + adj load. 256 threads, all 8 heads.
// smem ~44.3KB, 5 blocks/SM.
// ---------------------------------------------------------------------------
__global__ __launch_bounds__(256, 5) void softmax5(
    const float* __restrict__ eptr, const int* __restrict__ adj)
{
    __shared__ float es[128 * 68];   // 34816 B
    __shared__ float sS1[8 * 128];   // 4096 B  [h][k]
    __shared__ float gT[512];        // [j][h]; reused for wsum q3 partials
    __shared__ float aT[1024];       // dot partials / alpha / wsum q1,q2 partials
    __shared__ float redM[32];
    __shared__ float redS[32];

    const int bq = blockIdx.x;
    const int b  = bq >> 7, q = bq & 127;
    const int t  = threadIdx.x;
    const int lane = t & 31, warp = t >> 5;

    const uint32_t esb  = smem_u32(es);
    const uint32_t s1b  = smem_u32(sS1);

    // --- issue async streams: es tile + dS1 slab ---
    const float* erow = eptr + (size_t)bq * LL * EE;
    #pragma unroll
    for (int r = 0; r < 8; r++) {
        int idx = t + r * 256;
        int k   = idx >> 4;
        int j4  = (idx & 15) << 2;
        cp16(esb + (uint32_t)(k * 68 + j4) * 4u, erow + k * EE + j4);
    }
    {   // dS1[b*8+h][q][k4..k4+3] -> sS1[h][k4..]
        int h  = t >> 5;
        int k4 = (t & 31) << 2;
        cp16(s1b + (uint32_t)(h * 128 + k4) * 4u,
             dS1 + (((size_t)(b * HH + h)) * LL + q) * LL + k4);
    }
    cp_commit();

    // --- overlapped: gT transpose + adj ---
    #pragma unroll
    for (int i0 = 0; i0 < 2; i0++) {
        int i = t + i0 * 256;
        int h = i >> 6, j = i & 63;
        gT[j * 8 + h] = dG[(size_t)bq * 512 + i];
    }
    const int k  = t & 127;
    const int jh = t >> 7;
    int adjv = 1;
    if (t < 128) adjv = adj[(size_t)bq * LL + k];

    cp_wait<0>();
    __syncthreads();

    // ---- phase A: partial dots ----
    ull acc2[4] = {0, 0, 0, 0};
    #pragma unroll
    for (int j4 = 0; j4 < 8; j4++) {
        float4 ev4 = *(const float4*)(es + k * 68 + jh * 32 + j4 * 4);
        float evv[4] = {ev4.x, ev4.y, ev4.z, ev4.w};
        #pragma unroll
        for (int c = 0; c < 4; c++) {
            int j = jh * 32 + j4 * 4 + c;
            ull ed = pack2(evv[c], evv[c]);
            ulonglong2 g01 = *(const ulonglong2*)(gT + j * 8);
            ulonglong2 g23 = *(const ulonglong2*)(gT + j * 8 + 4);
            fma2(acc2[0], ed, g01.x); fma2(acc2[1], ed, g01.y);
            fma2(acc2[2], ed, g23.x); fma2(acc2[3], ed, g23.y);
        }
    }
    if (jh == 1) {
        *(ulonglong2*)(aT + k * 8)     = make_ulonglong2(acc2[0], acc2[1]);
        *(ulonglong2*)(aT + k * 8 + 4) = make_ulonglong2(acc2[2], acc2[3]);
    }
    __syncthreads();

    // ---- phase B: softmax (t<128, key k=t) ----
    float sv[8];
    if (t < 128) {
        ulonglong2 p01 = *(const ulonglong2*)(aT + k * 8);
        ulonglong2 p23 = *(const ulonglong2*)(aT + k * 8 + 4);
        add2(acc2[0], p01.x); add2(acc2[1], p01.y);
        add2(acc2[2], p23.x); add2(acc2[3], p23.y);
        unpack2(acc2[0], sv[0], sv[1]);
        unpack2(acc2[1], sv[2], sv[3]);
        unpack2(acc2[2], sv[4], sv[5]);
        unpack2(acc2[3], sv[6], sv[7]);
        #pragma unroll
        for (int h = 0; h < HH; h++) {
            float s = (sS1[h * 128 + k] + sv[h]) * 0.125f;
            s = (s > 0.f) ? s : 0.2f * s;
            if (adjv == 0) s = -1e9f;
            sv[h] = s;
        }
        #pragma unroll
        for (int h = 0; h < HH; h++) {
            float m = sv[h];
            #pragma unroll
            for (int o = 16; o > 0; o >>= 1) m = fmaxf(m, __shfl_xor_sync(0xffffffffu, m, o));
            if (lane == 0) redM[warp * 8 + h] = m;
        }
    }
    __syncthreads();

    float p[8];
    if (t < 128) {
        #pragma unroll
        for (int h = 0; h < HH; h++) {
            float mx = fmaxf(fmaxf(redM[h], redM[8 + h]), fmaxf(redM[16 + h], redM[24 + h]));
            p[h] = __expf(sv[h] - mx);
        }
        #pragma unroll
        for (int h = 0; h < HH; h++) {
            float s = p[h];
            #pragma unroll
            for (int o = 16; o > 0; o >>= 1) s += __shfl_xor_sync(0xffffffffu, s, o);
            if (lane == 0) redS[warp * 8 + h] = s;
        }
    }
    __syncthreads();

    if (t < 128) {
        float al[8];
        #pragma unroll
        for (int h = 0; h < HH; h++) {
            float tot = redS[h] + redS[8 + h] + redS[16 + h] + redS[24 + h];
            al[h] = p[h] / tot;
            dALPHA[(((size_t)(b * HH + h)) * LL + q) * LL + k] = al[h];
        }
        *(float4*)(aT + k * 8)     = make_float4(al[0], al[1], al[2], al[3]);
        *(float4*)(aT + k * 8 + 4) = make_float4(al[4], al[5], al[6], al[7]);
    }
    __syncthreads();

    // ---- phase C: Wsum ----
    const int ei = t & 63, qt = t >> 6;
    ull w2[4] = {0, 0, 0, 0};
    #pragma unroll 8
    for (int kk = 0; kk < 32; kk++) {
        int kq = qt * 32 + kk;
        float ev = es[kq * 68 + ei];
        ull ed = pack2(ev, ev);
        ulonglong2 a01 = *(const ulonglong2*)(aT + kq * 8);
        ulonglong2 a23 = *(const ulonglong2*)(aT + kq * 8 + 4);
        fma2(w2[0], ed, a01.x); fma2(w2[1], ed, a01.y);
        fma2(w2[2], ed, a23.x); fma2(w2[3], ed, a23.y);
    }
    __syncthreads();

    if (qt == 1) {
        *(ulonglong2*)(aT + ei * 8)       = make_ulonglong2(w2[0], w2[1]);
        *(ulonglong2*)(aT + ei * 8 + 4)   = make_ulonglong2(w2[2], w2[3]);
    } else if (qt == 2) {
        *(ulonglong2*)(aT + 512 + ei * 8)     = make_ulonglong2(w2[0], w2[1]);
        *(ulonglong2*)(aT + 512 + ei * 8 + 4) = make_ulonglong2(w2[2], w2[3]);
    } else if (qt == 3) {
        *(ulonglong2*)(gT + ei * 8)       = make_ulonglong2(w2[0], w2[1]);
        *(ulonglong2*)(gT + ei * 8 + 4)   = make_ulonglong2(w2[2], w2[3]);
    }
    __syncthreads();

    if (qt == 0) {
        ulonglong2 s1a = *(const ulonglong2*)(aT + ei * 8);
        ulonglong2 s1b2 = *(const ulonglong2*)(aT + ei * 8 + 4);
        ulonglong2 s2a = *(const ulonglong2*)(aT + 512 + ei * 8);
        ulonglong2 s2b = *(const ulonglong2*)(aT + 512 + ei * 8 + 4);
        ulonglong2 s3a = *(const ulonglong2*)(gT + ei * 8);
        ulonglong2 s3b = *(const ulonglong2*)(gT + ei * 8 + 4);
        add2(w2[0], s1a.x); add2(w2[1], s1a.y); add2(w2[2], s1b2.x); add2(w2[3], s1b2.y);
        add2(w2[0], s2a.x); add2(w2[1], s2a.y); add2(w2[2], s2b.x);  add2(w2[3], s2b.y);
        add2(w2[0], s3a.x); add2(w2[1], s3a.y); add2(w2[2], s3b.x);  add2(w2[3], s3b.y);
        float w[8];
        unpack2(w2[0], w[0], w[1]); unpack2(w2[1], w[2], w[3]);
        unpack2(w2[2], w[4], w[5]); unpack2(w2[3], w[6], w[7]);
        #pragma unroll
        for (int h = 0; h < HH; h++)
            dWsum[(((size_t)(b * HH + h)) * LL + q) * EE + ei] = w[h];
    }
}

// ---------------------------------------------------------------------------
// LayerNorm + ReLU per row of 512
// ---------------------------------------------------------------------------
__global__ __launch_bounds__(256) void ln_kernel(
    const float* __restrict__ gamma, const float* __restrict__ beta,
    float* __restrict__ out)
{
    const int r = blockIdx.x;
    const int t = threadIdx.x;
    const int lane = t & 31, warp = t >> 5;

    float v0 = dFFN[(size_t)r * DD + t];
    float v1 = dFFN[(size_t)r * DD + 256 + t];
    float s  = v0 + v1;
    float sq = v0 * v0 + v1 * v1;

    __shared__ float rs[8], rq[8];
    __shared__ float mu_s, rstd_s;
    #pragma unroll
    for (int o = 16; o > 0; o >>= 1) {
        s  += __shfl_xor_sync(0xffffffffu, s, o);
        sq += __shfl_xor_sync(0xffffffffu, sq, o);
    }
    if (lane == 0) { rs[warp] = s; rq[warp] = sq; }
    __syncthreads();
    if (t == 0) {
        float S = 0.f, Q2 = 0.f;
        #pragma unroll
        for (int w = 0; w < 8; w++) { S += rs[w]; Q2 += rq[w]; }
        float mu  = S / 512.f;
        float var = Q2 / 512.f - mu * mu;
        mu_s = mu;
        rstd_s = rsqrtf(var + 1e-5f);
    }
    __syncthreads();
    float mu = mu_s, rstd = rstd_s;

    float y0 = (v0 - mu) * rstd * gamma[t]       + beta[t];
    float y1 = (v1 - mu) * rstd * gamma[256 + t] + beta[256 + t];
    out[(size_t)r * DD + t]       = fmaxf(y0, 0.f);
    out[(size_t)r * DD + 256 + t] = fmaxf(y1, 0.f);
}

// ---------------------------------------------------------------------------
extern "C" void kernel_launch(void* const* d_in, const int* in_sizes, int n_in,
                              void* d_out, int out_size)
{
    const float* x     = (const float*)d_in[0];
    const int*   adj   = (const int*)  d_in[1];
    const float* e     = (const float*)d_in[2];
    const float* Wq    = (const float*)d_in[3];
    const float* Wkv   = (const float*)d_in[4];
    const float* We    = (const float*)d_in[5];
    const float* Wf    = (const float*)d_in[6];
    const float* bf    = (const float*)d_in[7];
    const float* gamma = (const float*)d_in[8];
    const float* beta  = (const float*)d_in[9];
    float* out = (float*)d_out;

    float *pQ, *pKV, *pATTN, *pFFN;
    cudaGetSymbolAddress((void**)&pQ,    dQ);
    cudaGetSymbolAddress((void**)&pKV,   dKV);
    cudaGetSymbolAddress((void**)&pATTN, dATTN);
    cudaGetSymbolAddress((void**)&pFFN,  dFFN);

    // 1. Q = x@Wq, KV = x@Wkv (cp.async)
    gemm_ca<<<dim3(DD/64, BL/64, 2), 128>>>(x, Wq, pQ, Wkv, pKV, nullptr, DD, DD);
    // 2+3. S1 and g merged into one launch (fills the chip better)
    s1g_kernel<<<256, 256>>>(We);
    // 4. softmax (cp.async streaming)
    softmax5<<<BL, 256>>>(e, adj);
    // 5. attention output (cp.async GEMM)
    attn_ca<<<dim3(BB*HH, 2), 128>>>(We);
    // 6. FFN GEMM with bias (cp.async)
    gemm_ca<<<dim3(DD/64, BL/64, 1), 128>>>(pATTN, Wf, pFFN, nullptr, nullptr, bf, DD, DD);
    // 7. LayerNorm + ReLU
    ln_kernel<<<BL, 256>>>(gamma, beta, out);
}